// round 1
// baseline (speedup 1.0000x reference)
#include <cuda_runtime.h>
#include <math.h>

#define BB 2
#define NN 2048
#define DD 1024
#define HH 16
#define DHH 64
#define M_TOTAL (BB * NN)   // 4096

// Scratch (allocation-free rule: __device__ globals)
__device__ float g_q[M_TOTAL * DD];
__device__ float g_k[M_TOTAL * DD];
__device__ float g_v[M_TOTAL * DD];
__device__ float g_ctx[M_TOTAL * DD];

// ---------------------------------------------------------------------------
// Tiled SGEMM: Y[M, Nd] = X[M, K] @ W[Nd, K]^T + bias
// Block tile 128x128, K-chunk 16, 256 threads, 8x8 per thread (strided map).
// ---------------------------------------------------------------------------
#define BM 128
#define BN 128
#define BK 16
#define LDA (BM + 1)
#define LDB (BN + 1)

__global__ __launch_bounds__(256, 2)
void gemm_bias_kernel(const float* __restrict__ X, const float* __restrict__ W,
                      const float* __restrict__ bias, float* __restrict__ Y,
                      int M, int Nd, int K) {
    __shared__ float As[BK][LDA];
    __shared__ float Bs[BK][LDB];

    const int tid = threadIdx.x;
    const int tx = tid & 15;        // 0..15
    const int ty = tid >> 4;        // 0..15
    const int rowBase = blockIdx.y * BM;
    const int colBase = blockIdx.x * BN;

    float acc[8][8];
#pragma unroll
    for (int i = 0; i < 8; i++)
#pragma unroll
        for (int j = 0; j < 8; j++) acc[i][j] = 0.f;

    for (int k0 = 0; k0 < K; k0 += BK) {
        // Load A tile (BM x BK) and B tile (BN x BK), both K-major in gmem.
#pragma unroll
        for (int p = 0; p < 8; p++) {
            int idx = p * 256 + tid;       // 0..2047
            int kk = idx & 15;
            int r = idx >> 4;              // 0..127
            As[kk][r] = X[(size_t)(rowBase + r) * K + k0 + kk];
            Bs[kk][r] = W[(size_t)(colBase + r) * K + k0 + kk];
        }
        __syncthreads();

#pragma unroll
        for (int kk = 0; kk < BK; kk++) {
            float a[8], b[8];
#pragma unroll
            for (int i = 0; i < 8; i++) a[i] = As[kk][ty + 16 * i];
#pragma unroll
            for (int j = 0; j < 8; j++) b[j] = Bs[kk][tx + 16 * j];
#pragma unroll
            for (int i = 0; i < 8; i++)
#pragma unroll
                for (int j = 0; j < 8; j++) acc[i][j] += a[i] * b[j];
        }
        __syncthreads();
    }

#pragma unroll
    for (int j = 0; j < 8; j++) {
        int col = colBase + tx + 16 * j;
        float bv = bias[col];
#pragma unroll
        for (int i = 0; i < 8; i++) {
            int row = rowBase + ty + 16 * i;
            Y[(size_t)row * Nd + col] = acc[i][j] + bv;
        }
    }
}

// ---------------------------------------------------------------------------
// Flash-style attention: one block per (b*H + h, query tile of 64).
// 256 threads. K/V tiles 64xDH in smem, online softmax, O in registers.
// q/k/v layouts: [B*N, D], head h occupies columns [h*DH, (h+1)*DH).
// ---------------------------------------------------------------------------
#define QT 64   // queries per block
#define KT 64   // keys per tile
#define LDS_P 65

__global__ __launch_bounds__(256, 3)
void attn_kernel(const float* __restrict__ q, const float* __restrict__ k,
                 const float* __restrict__ v, float* __restrict__ ctx) {
    extern __shared__ float sm[];
    float* Qs = sm;                       // QT * 65
    float* Ks = Qs + QT * LDS_P;          // KT * 65
    float* Vs = Ks + KT * LDS_P;          // KT * 65
    float* Ps = Vs + KT * LDS_P;          // QT * 65
    float* m_sm = Ps + QT * LDS_P;        // QT
    float* l_sm = m_sm + QT;              // QT
    float* alpha_sm = l_sm + QT;          // QT

    const int tid = threadIdx.x;
    const int tx = tid & 15;
    const int ty = tid >> 4;
    const int bh = blockIdx.x;            // 0..B*H-1
    const int b = bh / HH;
    const int h = bh % HH;
    const int qBase = blockIdx.y * QT;
    const float scale = 0.125f;           // 1/sqrt(64)

    // Load Q tile: rows qBase..qBase+63, cols h*DH..h*DH+63
    {
        const float* qsrc = q + ((size_t)(b * NN + qBase)) * DD + h * DHH;
#pragma unroll
        for (int p = 0; p < 16; p++) {
            int idx = p * 256 + tid;      // 0..4095
            int d = idx & 63;
            int r = idx >> 6;
            Qs[r * LDS_P + d] = qsrc[(size_t)r * DD + d];
        }
    }
    if (tid < QT) { m_sm[tid] = -INFINITY; l_sm[tid] = 0.f; }

    float o[4][4];
#pragma unroll
    for (int i = 0; i < 4; i++)
#pragma unroll
        for (int j = 0; j < 4; j++) o[i][j] = 0.f;

    for (int kt = 0; kt < NN; kt += KT) {
        __syncthreads();   // protect Ks/Vs (prev iter reads done)

        // Load K,V tiles
        const float* ksrc = k + ((size_t)(b * NN + kt)) * DD + h * DHH;
        const float* vsrc = v + ((size_t)(b * NN + kt)) * DD + h * DHH;
#pragma unroll
        for (int p = 0; p < 16; p++) {
            int idx = p * 256 + tid;
            int d = idx & 63;
            int r = idx >> 6;
            Ks[r * LDS_P + d] = ksrc[(size_t)r * DD + d];
            Vs[r * LDS_P + d] = vsrc[(size_t)r * DD + d];
        }
        __syncthreads();

        // S = scale * Q K^T  -> Ps  (each thread: rows ty+16i, cols tx+16j)
        {
            float s[4][4];
#pragma unroll
            for (int i = 0; i < 4; i++)
#pragma unroll
                for (int j = 0; j < 4; j++) s[i][j] = 0.f;
#pragma unroll
            for (int d = 0; d < DHH; d++) {
                float a[4], bb[4];
#pragma unroll
                for (int i = 0; i < 4; i++) a[i] = Qs[(ty + 16 * i) * LDS_P + d];
#pragma unroll
                for (int j = 0; j < 4; j++) bb[j] = Ks[(tx + 16 * j) * LDS_P + d];
#pragma unroll
                for (int i = 0; i < 4; i++)
#pragma unroll
                    for (int j = 0; j < 4; j++) s[i][j] += a[i] * bb[j];
            }
#pragma unroll
            for (int i = 0; i < 4; i++)
#pragma unroll
                for (int j = 0; j < 4; j++)
                    Ps[(ty + 16 * i) * LDS_P + (tx + 16 * j)] = s[i][j] * scale;
        }
        __syncthreads();

        // Online softmax: 4 threads per row (quad), 16 cols each.
        {
            int row = tid >> 2;
            int part = tid & 3;
            float m_old = m_sm[row];
            float l_old = l_sm[row];
            float lm = -INFINITY;
            int c0 = part * 16;
#pragma unroll
            for (int c = 0; c < 16; c++) lm = fmaxf(lm, Ps[row * LDS_P + c0 + c]);
            lm = fmaxf(lm, __shfl_xor_sync(0xffffffffu, lm, 1));
            lm = fmaxf(lm, __shfl_xor_sync(0xffffffffu, lm, 2));
            float m_new = fmaxf(m_old, lm);
            float lsum = 0.f;
#pragma unroll
            for (int c = 0; c < 16; c++) {
                float p = __expf(Ps[row * LDS_P + c0 + c] - m_new);
                Ps[row * LDS_P + c0 + c] = p;
                lsum += p;
            }
            lsum += __shfl_xor_sync(0xffffffffu, lsum, 1);
            lsum += __shfl_xor_sync(0xffffffffu, lsum, 2);
            if (part == 0) {
                float alpha = __expf(m_old - m_new);
                m_sm[row] = m_new;
                l_sm[row] = l_old * alpha + lsum;
                alpha_sm[row] = alpha;
            }
        }
        __syncthreads();

        // O = O*alpha + P V   (each thread: rows ty+16i, cols tx+16j of DH)
        {
#pragma unroll
            for (int i = 0; i < 4; i++) {
                float al = alpha_sm[ty + 16 * i];
#pragma unroll
                for (int j = 0; j < 4; j++) o[i][j] *= al;
            }
            for (int c = 0; c < KT; c++) {
                float a[4], bb[4];
#pragma unroll
                for (int i = 0; i < 4; i++) a[i] = Ps[(ty + 16 * i) * LDS_P + c];
#pragma unroll
                for (int j = 0; j < 4; j++) bb[j] = Vs[c * LDS_P + tx + 16 * j];
#pragma unroll
                for (int i = 0; i < 4; i++)
#pragma unroll
                    for (int j = 0; j < 4; j++) o[i][j] += a[i] * bb[j];
            }
        }
    }

    // Normalize and write ctx
#pragma unroll
    for (int i = 0; i < 4; i++) {
        int row = ty + 16 * i;
        float inv_l = 1.0f / l_sm[row];
#pragma unroll
        for (int j = 0; j < 4; j++) {
            int col = tx + 16 * j;
            ctx[((size_t)(b * NN + qBase + row)) * DD + h * DHH + col] = o[i][j] * inv_l;
        }
    }
}

// ---------------------------------------------------------------------------
// Launch
// ---------------------------------------------------------------------------
extern "C" void kernel_launch(void* const* d_in, const int* in_sizes, int n_in,
                              void* d_out, int out_size) {
    const float* x  = (const float*)d_in[0];
    const float* Wq = (const float*)d_in[1];
    const float* bq = (const float*)d_in[2];
    const float* Wk = (const float*)d_in[3];
    const float* bk = (const float*)d_in[4];
    const float* Wv = (const float*)d_in[5];
    const float* bv = (const float*)d_in[6];
    const float* Wo = (const float*)d_in[7];
    const float* bo = (const float*)d_in[8];
    float* out = (float*)d_out;

    float *qp, *kp, *vp, *cp;
    cudaGetSymbolAddress((void**)&qp, g_q);
    cudaGetSymbolAddress((void**)&kp, g_k);
    cudaGetSymbolAddress((void**)&vp, g_v);
    cudaGetSymbolAddress((void**)&cp, g_ctx);

    dim3 gemmGrid(DD / BN, M_TOTAL / BM);   // (8, 32)
    gemm_bias_kernel<<<gemmGrid, 256>>>(x, Wq, bq, qp, M_TOTAL, DD, DD);
    gemm_bias_kernel<<<gemmGrid, 256>>>(x, Wk, bk, kp, M_TOTAL, DD, DD);
    gemm_bias_kernel<<<gemmGrid, 256>>>(x, Wv, bv, vp, M_TOTAL, DD, DD);

    size_t attnSmem = (4 * QT * LDS_P + 3 * QT) * sizeof(float);  // ~67 KB
    cudaFuncSetAttribute(attn_kernel, cudaFuncAttributeMaxDynamicSharedMemorySize,
                         (int)attnSmem);
    dim3 attnGrid(BB * HH, NN / QT);        // (32, 32)
    attn_kernel<<<attnGrid, 256, attnSmem>>>(qp, kp, vp, cp);

    gemm_bias_kernel<<<gemmGrid, 256>>>(cp, Wo, bo, out, M_TOTAL, DD, DD);
}

// round 3
// speedup vs baseline: 1.5314x; 1.5314x over previous
#include <cuda_runtime.h>
#include <math.h>
#include <stdint.h>

#define BB 2
#define NN 2048
#define DD 1024
#define HH 16
#define DHH 64
#define M_TOTAL (BB * NN)   // 4096

// Scratch (allocation-free rule: __device__ globals)
__device__ float g_q[M_TOTAL * DD];
__device__ float g_k[M_TOTAL * DD];
__device__ float g_v[M_TOTAL * DD];
__device__ float g_ctx[M_TOTAL * DD];

// ---------------------------------------------------------------------------
// tf32 mma.sync helper (sm_80+ path — compiles for base sm_103 target)
// ---------------------------------------------------------------------------
__device__ __forceinline__ float to_tf32(float x) {
    float r;
    asm("cvt.rna.tf32.f32 %0, %1;" : "=f"(r) : "f"(x));
    return r;
}

__device__ __forceinline__ void mma_tf32(float* c, const uint32_t* a,
                                         const uint32_t* b) {
    asm volatile(
        "mma.sync.aligned.m16n8k8.row.col.f32.tf32.tf32.f32 "
        "{%0,%1,%2,%3}, {%4,%5,%6,%7}, {%8,%9}, {%0,%1,%2,%3};"
        : "+f"(c[0]), "+f"(c[1]), "+f"(c[2]), "+f"(c[3])
        : "r"(a[0]), "r"(a[1]), "r"(a[2]), "r"(a[3]), "r"(b[0]), "r"(b[1]));
}

// ---------------------------------------------------------------------------
// tf32 tensor-core GEMM: Y[M, Nd] = X[M, K] @ W[Nd, K]^T + bias
// CTA tile 128x128, K-chunk 32, 256 threads = 8 warps (2x4 warp grid),
// warp tile 64x32 = 4x4 m16n8k8 fragments. Smem stride 36 -> conflict-free.
// ---------------------------------------------------------------------------
#define GBM 128
#define GBN 128
#define GBK 32
#define GLD 36

__global__ __launch_bounds__(256, 2)
void gemm_mma_kernel(const float* __restrict__ X, const float* __restrict__ W,
                     const float* __restrict__ bias, float* __restrict__ Y,
                     int M, int Nd, int K) {
    __shared__ float As[GBM][GLD];
    __shared__ float Bs[GBN][GLD];

    const int tid = threadIdx.x;
    const int wid = tid >> 5;
    const int lane = tid & 31;
    const int g = lane >> 2;        // 0..7
    const int tg = lane & 3;        // 0..3
    const int wm = wid & 1;         // 2 warps along M
    const int wn = wid >> 1;        // 4 warps along N

    const int rowBase = blockIdx.y * GBM;
    const int colBase = blockIdx.x * GBN;

    float c[4][4][4];
#pragma unroll
    for (int mi = 0; mi < 4; mi++)
#pragma unroll
        for (int ni = 0; ni < 4; ni++)
#pragma unroll
            for (int r = 0; r < 4; r++) c[mi][ni][r] = 0.f;

    for (int k0 = 0; k0 < K; k0 += GBK) {
        // Load A/B tiles (128x32 each), rounding to tf32 on the way in.
#pragma unroll
        for (int p = 0; p < 4; p++) {
            int idx = p * 256 + tid;      // 0..1023 float4 chunks
            int row = idx >> 3;
            int c4 = idx & 7;
            float4 a = *reinterpret_cast<const float4*>(
                X + (size_t)(rowBase + row) * K + k0 + c4 * 4);
            As[row][c4 * 4 + 0] = to_tf32(a.x);
            As[row][c4 * 4 + 1] = to_tf32(a.y);
            As[row][c4 * 4 + 2] = to_tf32(a.z);
            As[row][c4 * 4 + 3] = to_tf32(a.w);
            float4 b = *reinterpret_cast<const float4*>(
                W + (size_t)(colBase + row) * K + k0 + c4 * 4);
            Bs[row][c4 * 4 + 0] = to_tf32(b.x);
            Bs[row][c4 * 4 + 1] = to_tf32(b.y);
            Bs[row][c4 * 4 + 2] = to_tf32(b.z);
            Bs[row][c4 * 4 + 3] = to_tf32(b.w);
        }
        __syncthreads();

#pragma unroll
        for (int kk = 0; kk < GBK / 8; kk++) {
            uint32_t afrag[4][4];
            uint32_t bfrag[4][2];
            const int kc = kk * 8;
#pragma unroll
            for (int mi = 0; mi < 4; mi++) {
                int r = wm * 64 + mi * 16 + g;
                afrag[mi][0] = __float_as_uint(As[r][kc + tg]);
                afrag[mi][1] = __float_as_uint(As[r + 8][kc + tg]);
                afrag[mi][2] = __float_as_uint(As[r][kc + tg + 4]);
                afrag[mi][3] = __float_as_uint(As[r + 8][kc + tg + 4]);
            }
#pragma unroll
            for (int ni = 0; ni < 4; ni++) {
                int n = wn * 32 + ni * 8 + g;
                bfrag[ni][0] = __float_as_uint(Bs[n][kc + tg]);
                bfrag[ni][1] = __float_as_uint(Bs[n][kc + tg + 4]);
            }
#pragma unroll
            for (int mi = 0; mi < 4; mi++)
#pragma unroll
                for (int ni = 0; ni < 4; ni++)
                    mma_tf32(c[mi][ni], afrag[mi], bfrag[ni]);
        }
        __syncthreads();
    }

    // Epilogue: c0/c1 at (row, col..col+1), c2/c3 at (row+8, ...)
#pragma unroll
    for (int mi = 0; mi < 4; mi++) {
        int row0 = rowBase + wm * 64 + mi * 16 + g;
#pragma unroll
        for (int ni = 0; ni < 4; ni++) {
            int col = colBase + wn * 32 + ni * 8 + tg * 2;
            float2 bv = *reinterpret_cast<const float2*>(bias + col);
            float2 o0, o1;
            o0.x = c[mi][ni][0] + bv.x;
            o0.y = c[mi][ni][1] + bv.y;
            o1.x = c[mi][ni][2] + bv.x;
            o1.y = c[mi][ni][3] + bv.y;
            *reinterpret_cast<float2*>(Y + (size_t)row0 * Nd + col) = o0;
            *reinterpret_cast<float2*>(Y + (size_t)(row0 + 8) * Nd + col) = o1;
        }
    }
}

// ---------------------------------------------------------------------------
// Flash-style attention (unchanged from round 1)
// ---------------------------------------------------------------------------
#define QT 64
#define KT 64
#define LDS_P 65

__global__ __launch_bounds__(256, 3)
void attn_kernel(const float* __restrict__ q, const float* __restrict__ k,
                 const float* __restrict__ v, float* __restrict__ ctx) {
    extern __shared__ float sm[];
    float* Qs = sm;
    float* Ks = Qs + QT * LDS_P;
    float* Vs = Ks + KT * LDS_P;
    float* Ps = Vs + KT * LDS_P;
    float* m_sm = Ps + QT * LDS_P;
    float* l_sm = m_sm + QT;
    float* alpha_sm = l_sm + QT;

    const int tid = threadIdx.x;
    const int tx = tid & 15;
    const int ty = tid >> 4;
    const int bh = blockIdx.x;
    const int b = bh / HH;
    const int h = bh % HH;
    const int qBase = blockIdx.y * QT;
    const float scale = 0.125f;

    {
        const float* qsrc = q + ((size_t)(b * NN + qBase)) * DD + h * DHH;
#pragma unroll
        for (int p = 0; p < 16; p++) {
            int idx = p * 256 + tid;
            int d = idx & 63;
            int r = idx >> 6;
            Qs[r * LDS_P + d] = qsrc[(size_t)r * DD + d];
        }
    }
    if (tid < QT) { m_sm[tid] = -INFINITY; l_sm[tid] = 0.f; }

    float o[4][4];
#pragma unroll
    for (int i = 0; i < 4; i++)
#pragma unroll
        for (int j = 0; j < 4; j++) o[i][j] = 0.f;

    for (int kt = 0; kt < NN; kt += KT) {
        __syncthreads();

        const float* ksrc = k + ((size_t)(b * NN + kt)) * DD + h * DHH;
        const float* vsrc = v + ((size_t)(b * NN + kt)) * DD + h * DHH;
#pragma unroll
        for (int p = 0; p < 16; p++) {
            int idx = p * 256 + tid;
            int d = idx & 63;
            int r = idx >> 6;
            Ks[r * LDS_P + d] = ksrc[(size_t)r * DD + d];
            Vs[r * LDS_P + d] = vsrc[(size_t)r * DD + d];
        }
        __syncthreads();

        {
            float s[4][4];
#pragma unroll
            for (int i = 0; i < 4; i++)
#pragma unroll
                for (int j = 0; j < 4; j++) s[i][j] = 0.f;
#pragma unroll
            for (int d = 0; d < DHH; d++) {
                float a[4], bb[4];
#pragma unroll
                for (int i = 0; i < 4; i++) a[i] = Qs[(ty + 16 * i) * LDS_P + d];
#pragma unroll
                for (int j = 0; j < 4; j++) bb[j] = Ks[(tx + 16 * j) * LDS_P + d];
#pragma unroll
                for (int i = 0; i < 4; i++)
#pragma unroll
                    for (int j = 0; j < 4; j++) s[i][j] += a[i] * bb[j];
            }
#pragma unroll
            for (int i = 0; i < 4; i++)
#pragma unroll
                for (int j = 0; j < 4; j++)
                    Ps[(ty + 16 * i) * LDS_P + (tx + 16 * j)] = s[i][j] * scale;
        }
        __syncthreads();

        {
            int row = tid >> 2;
            int part = tid & 3;
            float m_old = m_sm[row];
            float l_old = l_sm[row];
            float lm = -INFINITY;
            int c0 = part * 16;
#pragma unroll
            for (int c = 0; c < 16; c++) lm = fmaxf(lm, Ps[row * LDS_P + c0 + c]);
            lm = fmaxf(lm, __shfl_xor_sync(0xffffffffu, lm, 1));
            lm = fmaxf(lm, __shfl_xor_sync(0xffffffffu, lm, 2));
            float m_new = fmaxf(m_old, lm);
            float lsum = 0.f;
#pragma unroll
            for (int c = 0; c < 16; c++) {
                float p = __expf(Ps[row * LDS_P + c0 + c] - m_new);
                Ps[row * LDS_P + c0 + c] = p;
                lsum += p;
            }
            lsum += __shfl_xor_sync(0xffffffffu, lsum, 1);
            lsum += __shfl_xor_sync(0xffffffffu, lsum, 2);
            if (part == 0) {
                float alpha = __expf(m_old - m_new);
                m_sm[row] = m_new;
                l_sm[row] = l_old * alpha + lsum;
                alpha_sm[row] = alpha;
            }
        }
        __syncthreads();

        {
#pragma unroll
            for (int i = 0; i < 4; i++) {
                float al = alpha_sm[ty + 16 * i];
#pragma unroll
                for (int j = 0; j < 4; j++) o[i][j] *= al;
            }
            for (int c = 0; c < KT; c++) {
                float a[4], bb[4];
#pragma unroll
                for (int i = 0; i < 4; i++) a[i] = Ps[(ty + 16 * i) * LDS_P + c];
#pragma unroll
                for (int j = 0; j < 4; j++) bb[j] = Vs[c * LDS_P + tx + 16 * j];
#pragma unroll
                for (int i = 0; i < 4; i++)
#pragma unroll
                    for (int j = 0; j < 4; j++) o[i][j] += a[i] * bb[j];
            }
        }
    }

#pragma unroll
    for (int i = 0; i < 4; i++) {
        int row = ty + 16 * i;
        float inv_l = 1.0f / l_sm[row];
#pragma unroll
        for (int j = 0; j < 4; j++) {
            int col = tx + 16 * j;
            ctx[((size_t)(b * NN + qBase + row)) * DD + h * DHH + col] = o[i][j] * inv_l;
        }
    }
}

// ---------------------------------------------------------------------------
// Launch
// ---------------------------------------------------------------------------
extern "C" void kernel_launch(void* const* d_in, const int* in_sizes, int n_in,
                              void* d_out, int out_size) {
    const float* x  = (const float*)d_in[0];
    const float* Wq = (const float*)d_in[1];
    const float* bq = (const float*)d_in[2];
    const float* Wk = (const float*)d_in[3];
    const float* bk = (const float*)d_in[4];
    const float* Wv = (const float*)d_in[5];
    const float* bv = (const float*)d_in[6];
    const float* Wo = (const float*)d_in[7];
    const float* bo = (const float*)d_in[8];
    float* out = (float*)d_out;

    float *qp, *kp, *vp, *cp;
    cudaGetSymbolAddress((void**)&qp, g_q);
    cudaGetSymbolAddress((void**)&kp, g_k);
    cudaGetSymbolAddress((void**)&vp, g_v);
    cudaGetSymbolAddress((void**)&cp, g_ctx);

    dim3 gemmGrid(DD / GBN, M_TOTAL / GBM);   // (8, 32)
    gemm_mma_kernel<<<gemmGrid, 256>>>(x, Wq, bq, qp, M_TOTAL, DD, DD);
    gemm_mma_kernel<<<gemmGrid, 256>>>(x, Wk, bk, kp, M_TOTAL, DD, DD);
    gemm_mma_kernel<<<gemmGrid, 256>>>(x, Wv, bv, vp, M_TOTAL, DD, DD);

    size_t attnSmem = (4 * QT * LDS_P + 3 * QT) * sizeof(float);
    cudaFuncSetAttribute(attn_kernel, cudaFuncAttributeMaxDynamicSharedMemorySize,
                         (int)attnSmem);
    dim3 attnGrid(BB * HH, NN / QT);
    attn_kernel<<<attnGrid, 256, attnSmem>>>(qp, kp, vp, cp);

    gemm_mma_kernel<<<gemmGrid, 256>>>(cp, Wo, bo, out, M_TOTAL, DD, DD);
}

// round 5
// speedup vs baseline: 3.2037x; 2.0920x over previous
#include <cuda_runtime.h>
#include <math.h>
#include <stdint.h>

#define BB 2
#define NN 2048
#define DD 1024
#define HH 16
#define DHH 64
#define M_TOTAL (BB * NN)   // 4096

// Scratch (allocation-free rule: __device__ globals)
__device__ float g_q[M_TOTAL * DD];
__device__ float g_k[M_TOTAL * DD];
__device__ float g_v[M_TOTAL * DD];
__device__ float g_ctx[M_TOTAL * DD];

// ---------------------------------------------------------------------------
// Helpers
// ---------------------------------------------------------------------------
__device__ __forceinline__ float to_tf32(float x) {
    float r;
    asm("cvt.rna.tf32.f32 %0, %1;" : "=f"(r) : "f"(x));
    return r;
}

__device__ __forceinline__ void mma_tf32(float* c, const uint32_t* a,
                                         const uint32_t* b) {
    asm volatile(
        "mma.sync.aligned.m16n8k8.row.col.f32.tf32.tf32.f32 "
        "{%0,%1,%2,%3}, {%4,%5,%6,%7}, {%8,%9}, {%0,%1,%2,%3};"
        : "+f"(c[0]), "+f"(c[1]), "+f"(c[2]), "+f"(c[3])
        : "r"(a[0]), "r"(a[1]), "r"(a[2]), "r"(a[3]), "r"(b[0]), "r"(b[1]));
}

// exp2 on the FMA/ALU pipes (no MUFU). |rel err| < 6e-5 for f in [-.5,.5].
__device__ __forceinline__ float fexp2(float y) {
    y = fmaxf(y, -120.0f);
    float t = y + 12582912.0f;                     // round-to-nearest integer
    int i = __float_as_int(t) - 0x4B400000;
    float f = y - (t - 12582912.0f);               // frac in [-0.5, 0.5]
    float p = 1.0f + f * (0.6931472f + f * (0.24022651f +
              f * (0.05550411f + f * 0.00961813f)));
    return __uint_as_float(__float_as_uint(p) + (i << 23));
}

// ---------------------------------------------------------------------------
// tf32 tensor-core GEMM: Y[M, Nd] = X[M, K] @ W[Nd, K]^T + bias  (round-3)
// ---------------------------------------------------------------------------
#define GBM 128
#define GBN 128
#define GBK 32
#define GLD 36

__global__ __launch_bounds__(256, 2)
void gemm_mma_kernel(const float* __restrict__ X, const float* __restrict__ W,
                     const float* __restrict__ bias, float* __restrict__ Y,
                     int M, int Nd, int K) {
    __shared__ float As[GBM][GLD];
    __shared__ float Bs[GBN][GLD];

    const int tid = threadIdx.x;
    const int wid = tid >> 5;
    const int lane = tid & 31;
    const int g = lane >> 2;
    const int tg = lane & 3;
    const int wm = wid & 1;
    const int wn = wid >> 1;

    const int rowBase = blockIdx.y * GBM;
    const int colBase = blockIdx.x * GBN;

    float c[4][4][4];
#pragma unroll
    for (int mi = 0; mi < 4; mi++)
#pragma unroll
        for (int ni = 0; ni < 4; ni++)
#pragma unroll
            for (int r = 0; r < 4; r++) c[mi][ni][r] = 0.f;

    for (int k0 = 0; k0 < K; k0 += GBK) {
#pragma unroll
        for (int p = 0; p < 4; p++) {
            int idx = p * 256 + tid;
            int row = idx >> 3;
            int c4 = idx & 7;
            float4 a = *reinterpret_cast<const float4*>(
                X + (size_t)(rowBase + row) * K + k0 + c4 * 4);
            As[row][c4 * 4 + 0] = to_tf32(a.x);
            As[row][c4 * 4 + 1] = to_tf32(a.y);
            As[row][c4 * 4 + 2] = to_tf32(a.z);
            As[row][c4 * 4 + 3] = to_tf32(a.w);
            float4 b = *reinterpret_cast<const float4*>(
                W + (size_t)(colBase + row) * K + k0 + c4 * 4);
            Bs[row][c4 * 4 + 0] = to_tf32(b.x);
            Bs[row][c4 * 4 + 1] = to_tf32(b.y);
            Bs[row][c4 * 4 + 2] = to_tf32(b.z);
            Bs[row][c4 * 4 + 3] = to_tf32(b.w);
        }
        __syncthreads();

#pragma unroll
        for (int kk = 0; kk < GBK / 8; kk++) {
            uint32_t afrag[4][4];
            uint32_t bfrag[4][2];
            const int kc = kk * 8;
#pragma unroll
            for (int mi = 0; mi < 4; mi++) {
                int r = wm * 64 + mi * 16 + g;
                afrag[mi][0] = __float_as_uint(As[r][kc + tg]);
                afrag[mi][1] = __float_as_uint(As[r + 8][kc + tg]);
                afrag[mi][2] = __float_as_uint(As[r][kc + tg + 4]);
                afrag[mi][3] = __float_as_uint(As[r + 8][kc + tg + 4]);
            }
#pragma unroll
            for (int ni = 0; ni < 4; ni++) {
                int n = wn * 32 + ni * 8 + g;
                bfrag[ni][0] = __float_as_uint(Bs[n][kc + tg]);
                bfrag[ni][1] = __float_as_uint(Bs[n][kc + tg + 4]);
            }
#pragma unroll
            for (int mi = 0; mi < 4; mi++)
#pragma unroll
                for (int ni = 0; ni < 4; ni++)
                    mma_tf32(c[mi][ni], afrag[mi], bfrag[ni]);
        }
        __syncthreads();
    }

#pragma unroll
    for (int mi = 0; mi < 4; mi++) {
        int row0 = rowBase + wm * 64 + mi * 16 + g;
#pragma unroll
        for (int ni = 0; ni < 4; ni++) {
            int col = colBase + wn * 32 + ni * 8 + tg * 2;
            float2 bv = *reinterpret_cast<const float2*>(bias + col);
            float2 o0, o1;
            o0.x = c[mi][ni][0] + bv.x;
            o0.y = c[mi][ni][1] + bv.y;
            o1.x = c[mi][ni][2] + bv.x;
            o1.y = c[mi][ni][3] + bv.y;
            *reinterpret_cast<float2*>(Y + (size_t)row0 * Nd + col) = o0;
            *reinterpret_cast<float2*>(Y + (size_t)(row0 + 8) * Nd + col) = o1;
        }
    }
}

// ---------------------------------------------------------------------------
// Tensor-core flash attention.
// Block: 128 threads = 4 warps; qtile 64 (16 rows/warp); ktile 64.
// Q fragments register-resident; S/O accumulators in registers; softmax in
// registers (log2 domain, FFMA-pipe exp2). P round-trips via per-warp smem.
// Dynamic smem: Ps[64][68] | Ks[64][68] | Vs[64][72]  = 52 KB.
// ---------------------------------------------------------------------------
#define PLD 68   // Ps stride: A-frag read bank = 4g+tg  (perfect permutation)
#define KLD 68   // Ks stride: bank = 4g+tg              (perfect permutation)
#define VLD 72   // Vs stride: bank = 8tg+g              (perfect permutation)
#define ATTN_SMEM ((64 * PLD + 64 * KLD + 64 * VLD) * 4)

__global__ __launch_bounds__(128)
void attn_mma_kernel(const float* __restrict__ q, const float* __restrict__ k,
                     const float* __restrict__ v, float* __restrict__ ctx) {
    extern __shared__ float smf[];
    float* Ps = smf;                  // 64 x PLD (Q tile, then P tiles)
    float* Ks = Ps + 64 * PLD;        // 64 x KLD
    float* Vs = Ks + 64 * KLD;        // 64 x VLD

    const int tid = threadIdx.x;
    const int wid = tid >> 5;
    const int lane = tid & 31;
    const int g = lane >> 2;
    const int tg = lane & 3;
    const int wrow = wid * 16;

    const int bh = blockIdx.x;
    const int b = bh / HH;
    const int h = bh % HH;
    const int qBase = blockIdx.y * 64;

    const float cscale = 0.18033688f;   // (1/8) * log2(e)

    // ---- Load Q tile (64 x 64, tf32) into Ps ----
    {
        const float* qsrc = q + ((size_t)(b * NN + qBase)) * DD + h * DHH;
#pragma unroll
        for (int p = 0; p < 8; p++) {
            int idx = p * 128 + tid;      // 1024 float4 chunks
            int row = idx >> 4;
            int c4 = idx & 15;
            float4 a = *reinterpret_cast<const float4*>(qsrc + (size_t)row * DD + c4 * 4);
            Ps[row * PLD + c4 * 4 + 0] = to_tf32(a.x);
            Ps[row * PLD + c4 * 4 + 1] = to_tf32(a.y);
            Ps[row * PLD + c4 * 4 + 2] = to_tf32(a.z);
            Ps[row * PLD + c4 * 4 + 3] = to_tf32(a.w);
        }
    }
    __syncthreads();

    // ---- Q fragments (per warp: 16 rows x 64 k) -> registers ----
    uint32_t aQ[8][4];
#pragma unroll
    for (int kk = 0; kk < 8; kk++) {
        int kc = kk * 8;
        int r = wrow + g;
        aQ[kk][0] = __float_as_uint(Ps[r * PLD + kc + tg]);
        aQ[kk][1] = __float_as_uint(Ps[(r + 8) * PLD + kc + tg]);
        aQ[kk][2] = __float_as_uint(Ps[r * PLD + kc + tg + 4]);
        aQ[kk][3] = __float_as_uint(Ps[(r + 8) * PLD + kc + tg + 4]);
    }
    __syncthreads();   // done with Q in Ps; reuse as P buffer below

    float m0 = -1e30f, m1 = -1e30f, l0 = 0.f, l1 = 0.f;
    float O[8][4];
#pragma unroll
    for (int ni = 0; ni < 8; ni++)
#pragma unroll
        for (int r = 0; r < 4; r++) O[ni][r] = 0.f;

    for (int kt = 0; kt < NN; kt += 64) {
        __syncthreads();   // all warps done with prev K/V
        {
            const float* ksrc = k + ((size_t)(b * NN + kt)) * DD + h * DHH;
            const float* vsrc = v + ((size_t)(b * NN + kt)) * DD + h * DHH;
#pragma unroll
            for (int p = 0; p < 8; p++) {
                int idx = p * 128 + tid;
                int row = idx >> 4;
                int c4 = idx & 15;
                float4 a = *reinterpret_cast<const float4*>(ksrc + (size_t)row * DD + c4 * 4);
                Ks[row * KLD + c4 * 4 + 0] = to_tf32(a.x);
                Ks[row * KLD + c4 * 4 + 1] = to_tf32(a.y);
                Ks[row * KLD + c4 * 4 + 2] = to_tf32(a.z);
                Ks[row * KLD + c4 * 4 + 3] = to_tf32(a.w);
                float4 bv4 = *reinterpret_cast<const float4*>(vsrc + (size_t)row * DD + c4 * 4);
                Vs[row * VLD + c4 * 4 + 0] = to_tf32(bv4.x);
                Vs[row * VLD + c4 * 4 + 1] = to_tf32(bv4.y);
                Vs[row * VLD + c4 * 4 + 2] = to_tf32(bv4.z);
                Vs[row * VLD + c4 * 4 + 3] = to_tf32(bv4.w);
            }
        }
        __syncthreads();

        // ---- S = Q K^T (warp: 16 x 64) ----
        float S[8][4];
#pragma unroll
        for (int ni = 0; ni < 8; ni++)
#pragma unroll
            for (int r = 0; r < 4; r++) S[ni][r] = 0.f;
#pragma unroll
        for (int kk = 0; kk < 8; kk++) {
            int kc = kk * 8;
#pragma unroll
            for (int ni = 0; ni < 8; ni++) {
                uint32_t bK[2];
                int n = ni * 8 + g;
                bK[0] = __float_as_uint(Ks[n * KLD + kc + tg]);
                bK[1] = __float_as_uint(Ks[n * KLD + kc + tg + 4]);
                mma_tf32(S[ni], aQ[kk], bK);
            }
        }

        // ---- Online softmax in registers (log2 domain) ----
        float ym0 = -1e30f, ym1 = -1e30f;
#pragma unroll
        for (int ni = 0; ni < 8; ni++) {
            ym0 = fmaxf(ym0, fmaxf(S[ni][0], S[ni][1]));
            ym1 = fmaxf(ym1, fmaxf(S[ni][2], S[ni][3]));
        }
        ym0 = fmaxf(ym0, __shfl_xor_sync(0xffffffffu, ym0, 1));
        ym0 = fmaxf(ym0, __shfl_xor_sync(0xffffffffu, ym0, 2));
        ym1 = fmaxf(ym1, __shfl_xor_sync(0xffffffffu, ym1, 1));
        ym1 = fmaxf(ym1, __shfl_xor_sync(0xffffffffu, ym1, 2));
        float mn0 = fmaxf(m0, ym0 * cscale);
        float mn1 = fmaxf(m1, ym1 * cscale);
        float al0 = fexp2(m0 - mn0);
        float al1 = fexp2(m1 - mn1);

        float ls0 = 0.f, ls1 = 0.f;
        int r0 = wrow + g;
#pragma unroll
        for (int ni = 0; ni < 8; ni++) {
            float p0 = to_tf32(fexp2(fmaf(S[ni][0], cscale, -mn0)));
            float p1 = to_tf32(fexp2(fmaf(S[ni][1], cscale, -mn0)));
            float p2 = to_tf32(fexp2(fmaf(S[ni][2], cscale, -mn1)));
            float p3 = to_tf32(fexp2(fmaf(S[ni][3], cscale, -mn1)));
            ls0 += p0 + p1;
            ls1 += p2 + p3;
            int col = ni * 8 + tg * 2;
            *reinterpret_cast<float2*>(&Ps[r0 * PLD + col]) = make_float2(p0, p1);
            *reinterpret_cast<float2*>(&Ps[(r0 + 8) * PLD + col]) = make_float2(p2, p3);
        }
        ls0 += __shfl_xor_sync(0xffffffffu, ls0, 1);
        ls0 += __shfl_xor_sync(0xffffffffu, ls0, 2);
        ls1 += __shfl_xor_sync(0xffffffffu, ls1, 1);
        ls1 += __shfl_xor_sync(0xffffffffu, ls1, 2);

        l0 = l0 * al0 + ls0;
        l1 = l1 * al1 + ls1;
        m0 = mn0;
        m1 = mn1;
#pragma unroll
        for (int ni = 0; ni < 8; ni++) {
            O[ni][0] *= al0; O[ni][1] *= al0;
            O[ni][2] *= al1; O[ni][3] *= al1;
        }
        __syncwarp();

        // ---- O += P V (warp: 16 x 64) ----
#pragma unroll
        for (int kk = 0; kk < 8; kk++) {
            int kc = kk * 8;
            uint32_t aP[4];
            aP[0] = __float_as_uint(Ps[r0 * PLD + kc + tg]);
            aP[1] = __float_as_uint(Ps[(r0 + 8) * PLD + kc + tg]);
            aP[2] = __float_as_uint(Ps[r0 * PLD + kc + tg + 4]);
            aP[3] = __float_as_uint(Ps[(r0 + 8) * PLD + kc + tg + 4]);
#pragma unroll
            for (int ni = 0; ni < 8; ni++) {
                uint32_t bV[2];
                int n = ni * 8 + g;
                bV[0] = __float_as_uint(Vs[(kc + tg) * VLD + n]);
                bV[1] = __float_as_uint(Vs[(kc + tg + 4) * VLD + n]);
                mma_tf32(O[ni], aP, bV);
            }
        }
        __syncwarp();   // Ps reads done before next-iter P writes
    }

    // ---- Epilogue ----
    float inv0 = 1.0f / l0;
    float inv1 = 1.0f / l1;
    int row0 = qBase + wrow + g;
#pragma unroll
    for (int ni = 0; ni < 8; ni++) {
        int col = h * DHH + ni * 8 + tg * 2;
        float2 o0 = make_float2(O[ni][0] * inv0, O[ni][1] * inv0);
        float2 o1 = make_float2(O[ni][2] * inv1, O[ni][3] * inv1);
        *reinterpret_cast<float2*>(ctx + ((size_t)(b * NN + row0)) * DD + col) = o0;
        *reinterpret_cast<float2*>(ctx + ((size_t)(b * NN + row0 + 8)) * DD + col) = o1;
    }
}

// ---------------------------------------------------------------------------
// Launch
// ---------------------------------------------------------------------------
extern "C" void kernel_launch(void* const* d_in, const int* in_sizes, int n_in,
                              void* d_out, int out_size) {
    const float* x  = (const float*)d_in[0];
    const float* Wq = (const float*)d_in[1];
    const float* bq = (const float*)d_in[2];
    const float* Wk = (const float*)d_in[3];
    const float* bk = (const float*)d_in[4];
    const float* Wv = (const float*)d_in[5];
    const float* bv = (const float*)d_in[6];
    const float* Wo = (const float*)d_in[7];
    const float* bo = (const float*)d_in[8];
    float* out = (float*)d_out;

    float *qp, *kp, *vp, *cp;
    cudaGetSymbolAddress((void**)&qp, g_q);
    cudaGetSymbolAddress((void**)&kp, g_k);
    cudaGetSymbolAddress((void**)&vp, g_v);
    cudaGetSymbolAddress((void**)&cp, g_ctx);

    dim3 gemmGrid(DD / GBN, M_TOTAL / GBM);   // (8, 32)
    gemm_mma_kernel<<<gemmGrid, 256>>>(x, Wq, bq, qp, M_TOTAL, DD, DD);
    gemm_mma_kernel<<<gemmGrid, 256>>>(x, Wk, bk, kp, M_TOTAL, DD, DD);
    gemm_mma_kernel<<<gemmGrid, 256>>>(x, Wv, bv, vp, M_TOTAL, DD, DD);

    cudaFuncSetAttribute(attn_mma_kernel,
                         cudaFuncAttributeMaxDynamicSharedMemorySize, ATTN_SMEM);
    dim3 attnGrid(BB * HH, NN / 64);          // (32, 32)
    attn_mma_kernel<<<attnGrid, 128, ATTN_SMEM>>>(qp, kp, vp, cp);

    gemm_mma_kernel<<<gemmGrid, 256>>>(cp, Wo, bo, out, M_TOTAL, DD, DD);
}

// round 6
// speedup vs baseline: 3.4339x; 1.0719x over previous
#include <cuda_runtime.h>
#include <math.h>
#include <stdint.h>

#define BB 2
#define NN 2048
#define DD 1024
#define HH 16
#define DHH 64
#define M_TOTAL (BB * NN)   // 4096

// Scratch (allocation-free rule: __device__ globals)
__device__ float g_q[M_TOTAL * DD];
__device__ float g_k[M_TOTAL * DD];
__device__ float g_v[M_TOTAL * DD];
__device__ float g_ctx[M_TOTAL * DD];

// ---------------------------------------------------------------------------
// Helpers
// ---------------------------------------------------------------------------
__device__ __forceinline__ float to_tf32(float x) {
    float r;
    asm("cvt.rna.tf32.f32 %0, %1;" : "=f"(r) : "f"(x));
    return r;
}

__device__ __forceinline__ void mma_tf32(float* c, const uint32_t* a,
                                         const uint32_t* b) {
    asm volatile(
        "mma.sync.aligned.m16n8k8.row.col.f32.tf32.tf32.f32 "
        "{%0,%1,%2,%3}, {%4,%5,%6,%7}, {%8,%9}, {%0,%1,%2,%3};"
        : "+f"(c[0]), "+f"(c[1]), "+f"(c[2]), "+f"(c[3])
        : "r"(a[0]), "r"(a[1]), "r"(a[2]), "r"(a[3]), "r"(b[0]), "r"(b[1]));
}

// exp2 on the FMA/ALU pipes (no MUFU). |rel err| < 6e-5 for f in [-.5,.5].
__device__ __forceinline__ float fexp2(float y) {
    y = fmaxf(y, -120.0f);
    float t = y + 12582912.0f;                     // round-to-nearest integer
    int i = __float_as_int(t) - 0x4B400000;
    float f = y - (t - 12582912.0f);               // frac in [-0.5, 0.5]
    float p = 1.0f + f * (0.6931472f + f * (0.24022651f +
              f * (0.05550411f + f * 0.00961813f)));
    return __uint_as_float(__float_as_uint(p) + (i << 23));
}

// ---------------------------------------------------------------------------
// tf32 tensor-core GEMM body: Y[M, Nd] = X[M, K] @ W[Nd, K]^T + bias
// ---------------------------------------------------------------------------
#define GBM 128
#define GBN 128
#define GBK 32
#define GLD 36

__device__ __forceinline__
void gemm_body(const float* __restrict__ X, const float* __restrict__ W,
               const float* __restrict__ bias, float* __restrict__ Y,
               int M, int Nd, int K) {
    __shared__ float As[GBM][GLD];
    __shared__ float Bs[GBN][GLD];

    const int tid = threadIdx.x;
    const int wid = tid >> 5;
    const int lane = tid & 31;
    const int g = lane >> 2;
    const int tg = lane & 3;
    const int wm = wid & 1;
    const int wn = wid >> 1;

    const int rowBase = blockIdx.y * GBM;
    const int colBase = blockIdx.x * GBN;

    float c[4][4][4];
#pragma unroll
    for (int mi = 0; mi < 4; mi++)
#pragma unroll
        for (int ni = 0; ni < 4; ni++)
#pragma unroll
            for (int r = 0; r < 4; r++) c[mi][ni][r] = 0.f;

    for (int k0 = 0; k0 < K; k0 += GBK) {
#pragma unroll
        for (int p = 0; p < 4; p++) {
            int idx = p * 256 + tid;
            int row = idx >> 3;
            int c4 = idx & 7;
            float4 a = *reinterpret_cast<const float4*>(
                X + (size_t)(rowBase + row) * K + k0 + c4 * 4);
            As[row][c4 * 4 + 0] = to_tf32(a.x);
            As[row][c4 * 4 + 1] = to_tf32(a.y);
            As[row][c4 * 4 + 2] = to_tf32(a.z);
            As[row][c4 * 4 + 3] = to_tf32(a.w);
            float4 b = *reinterpret_cast<const float4*>(
                W + (size_t)(colBase + row) * K + k0 + c4 * 4);
            Bs[row][c4 * 4 + 0] = to_tf32(b.x);
            Bs[row][c4 * 4 + 1] = to_tf32(b.y);
            Bs[row][c4 * 4 + 2] = to_tf32(b.z);
            Bs[row][c4 * 4 + 3] = to_tf32(b.w);
        }
        __syncthreads();

#pragma unroll
        for (int kk = 0; kk < GBK / 8; kk++) {
            uint32_t afrag[4][4];
            uint32_t bfrag[4][2];
            const int kc = kk * 8;
#pragma unroll
            for (int mi = 0; mi < 4; mi++) {
                int r = wm * 64 + mi * 16 + g;
                afrag[mi][0] = __float_as_uint(As[r][kc + tg]);
                afrag[mi][1] = __float_as_uint(As[r + 8][kc + tg]);
                afrag[mi][2] = __float_as_uint(As[r][kc + tg + 4]);
                afrag[mi][3] = __float_as_uint(As[r + 8][kc + tg + 4]);
            }
#pragma unroll
            for (int ni = 0; ni < 4; ni++) {
                int n = wn * 32 + ni * 8 + g;
                bfrag[ni][0] = __float_as_uint(Bs[n][kc + tg]);
                bfrag[ni][1] = __float_as_uint(Bs[n][kc + tg + 4]);
            }
#pragma unroll
            for (int mi = 0; mi < 4; mi++)
#pragma unroll
                for (int ni = 0; ni < 4; ni++)
                    mma_tf32(c[mi][ni], afrag[mi], bfrag[ni]);
        }
        __syncthreads();
    }

#pragma unroll
    for (int mi = 0; mi < 4; mi++) {
        int row0 = rowBase + wm * 64 + mi * 16 + g;
#pragma unroll
        for (int ni = 0; ni < 4; ni++) {
            int col = colBase + wn * 32 + ni * 8 + tg * 2;
            float2 bv = *reinterpret_cast<const float2*>(bias + col);
            float2 o0, o1;
            o0.x = c[mi][ni][0] + bv.x;
            o0.y = c[mi][ni][1] + bv.y;
            o1.x = c[mi][ni][2] + bv.x;
            o1.y = c[mi][ni][3] + bv.y;
            *reinterpret_cast<float2*>(Y + (size_t)row0 * Nd + col) = o0;
            *reinterpret_cast<float2*>(Y + (size_t)(row0 + 8) * Nd + col) = o1;
        }
    }
}

__global__ __launch_bounds__(256, 2)
void gemm_mma_kernel(const float* __restrict__ X, const float* __restrict__ W,
                     const float* __restrict__ bias, float* __restrict__ Y,
                     int M, int Nd, int K) {
    gemm_body(X, W, bias, Y, M, Nd, K);
}

// Fused Q/K/V projection: blockIdx.z selects weight/bias/output.
__global__ __launch_bounds__(256, 2)
void gemm_qkv_kernel(const float* __restrict__ X,
                     const float* __restrict__ Wq, const float* __restrict__ Wk,
                     const float* __restrict__ Wv,
                     const float* __restrict__ bq, const float* __restrict__ bk,
                     const float* __restrict__ bv,
                     float* __restrict__ q, float* __restrict__ kk,
                     float* __restrict__ vv) {
    const int z = blockIdx.z;
    const float* W = (z == 0) ? Wq : (z == 1) ? Wk : Wv;
    const float* bias = (z == 0) ? bq : (z == 1) ? bk : bv;
    float* Y = (z == 0) ? q : (z == 1) ? kk : vv;
    gemm_body(X, W, bias, Y, M_TOTAL, DD, DD);
}

// ---------------------------------------------------------------------------
// Tensor-core flash attention v2.
// Block: 256 threads = 8 warps; qtile 128 (16 rows/warp); ktile 64.
// Register prefetch of next K/V tile; softmax in registers (log2, fexp2).
// Dynamic smem: Ps[128][68] | Ks[64][68] | Vs[64][72] = 69 KB.
// ---------------------------------------------------------------------------
#define PLD 68
#define KLD 68
#define VLD 72
#define ATTN_SMEM ((128 * PLD + 64 * KLD + 64 * VLD) * 4)

__global__ __launch_bounds__(256, 1)
void attn_mma_kernel(const float* __restrict__ q, const float* __restrict__ k,
                     const float* __restrict__ v, float* __restrict__ ctx) {
    extern __shared__ float smf[];
    float* Ps = smf;                   // 128 x PLD (Q tile, then P tiles)
    float* Ks = Ps + 128 * PLD;        // 64 x KLD
    float* Vs = Ks + 64 * KLD;         // 64 x VLD

    const int tid = threadIdx.x;
    const int wid = tid >> 5;
    const int lane = tid & 31;
    const int g = lane >> 2;
    const int tg = lane & 3;
    const int wrow = wid * 16;

    const int bh = blockIdx.x;
    const int b = bh / HH;
    const int h = bh % HH;
    const int qBase = blockIdx.y * 128;

    const float cscale = 0.18033688f;   // (1/8) * log2(e)

    // K/V load index mapping (64 rows x 16 float4 chunks = 1024 / 256 thr)
    const int lrow[4] = { (0 * 256 + tid) >> 4, (1 * 256 + tid) >> 4,
                          (2 * 256 + tid) >> 4, (3 * 256 + tid) >> 4 };
    const int lc4 = tid & 15;

    // ---- Load Q tile (128 x 64, tf32) into Ps ----
    {
        const float* qsrc = q + ((size_t)(b * NN + qBase)) * DD + h * DHH;
#pragma unroll
        for (int p = 0; p < 8; p++) {
            int idx = p * 256 + tid;      // 2048 float4 chunks
            int row = idx >> 4;
            int c4 = idx & 15;
            float4 a = *reinterpret_cast<const float4*>(qsrc + (size_t)row * DD + c4 * 4);
            Ps[row * PLD + c4 * 4 + 0] = to_tf32(a.x);
            Ps[row * PLD + c4 * 4 + 1] = to_tf32(a.y);
            Ps[row * PLD + c4 * 4 + 2] = to_tf32(a.z);
            Ps[row * PLD + c4 * 4 + 3] = to_tf32(a.w);
        }
    }
    __syncthreads();

    // ---- Q fragments (per warp: 16 rows x 64 k) -> registers ----
    uint32_t aQ[8][4];
#pragma unroll
    for (int kk = 0; kk < 8; kk++) {
        int kc = kk * 8;
        int r = wrow + g;
        aQ[kk][0] = __float_as_uint(Ps[r * PLD + kc + tg]);
        aQ[kk][1] = __float_as_uint(Ps[(r + 8) * PLD + kc + tg]);
        aQ[kk][2] = __float_as_uint(Ps[r * PLD + kc + tg + 4]);
        aQ[kk][3] = __float_as_uint(Ps[(r + 8) * PLD + kc + tg + 4]);
    }
    __syncthreads();   // done with Q in Ps; reuse as P buffer below

    const float* kbase = k + ((size_t)(b * NN)) * DD + h * DHH;
    const float* vbase = v + ((size_t)(b * NN)) * DD + h * DHH;

    // ---- Prefetch tile 0 into registers ----
    float4 kreg[4], vreg[4];
#pragma unroll
    for (int p = 0; p < 4; p++) {
        kreg[p] = *reinterpret_cast<const float4*>(kbase + (size_t)lrow[p] * DD + lc4 * 4);
        vreg[p] = *reinterpret_cast<const float4*>(vbase + (size_t)lrow[p] * DD + lc4 * 4);
    }

    float m0 = -1e30f, m1 = -1e30f, l0 = 0.f, l1 = 0.f;
    float O[8][4];
#pragma unroll
    for (int ni = 0; ni < 8; ni++)
#pragma unroll
        for (int r = 0; r < 4; r++) O[ni][r] = 0.f;

    for (int kt = 0; kt < NN; kt += 64) {
        // ---- Commit prefetched tile to smem (tf32 round) ----
#pragma unroll
        for (int p = 0; p < 4; p++) {
            int row = lrow[p];
            Ks[row * KLD + lc4 * 4 + 0] = to_tf32(kreg[p].x);
            Ks[row * KLD + lc4 * 4 + 1] = to_tf32(kreg[p].y);
            Ks[row * KLD + lc4 * 4 + 2] = to_tf32(kreg[p].z);
            Ks[row * KLD + lc4 * 4 + 3] = to_tf32(kreg[p].w);
            Vs[row * VLD + lc4 * 4 + 0] = to_tf32(vreg[p].x);
            Vs[row * VLD + lc4 * 4 + 1] = to_tf32(vreg[p].y);
            Vs[row * VLD + lc4 * 4 + 2] = to_tf32(vreg[p].z);
            Vs[row * VLD + lc4 * 4 + 3] = to_tf32(vreg[p].w);
        }
        __syncthreads();

        // ---- Prefetch next tile (covered by compute below) ----
        if (kt + 64 < NN) {
            const float* kn = kbase + (size_t)(kt + 64) * DD;
            const float* vn = vbase + (size_t)(kt + 64) * DD;
#pragma unroll
            for (int p = 0; p < 4; p++) {
                kreg[p] = *reinterpret_cast<const float4*>(kn + (size_t)lrow[p] * DD + lc4 * 4);
                vreg[p] = *reinterpret_cast<const float4*>(vn + (size_t)lrow[p] * DD + lc4 * 4);
            }
        }

        // ---- S = Q K^T (warp: 16 x 64) ----
        float S[8][4];
#pragma unroll
        for (int ni = 0; ni < 8; ni++)
#pragma unroll
            for (int r = 0; r < 4; r++) S[ni][r] = 0.f;
#pragma unroll
        for (int kk = 0; kk < 8; kk++) {
            int kc = kk * 8;
#pragma unroll
            for (int ni = 0; ni < 8; ni++) {
                uint32_t bK[2];
                int n = ni * 8 + g;
                bK[0] = __float_as_uint(Ks[n * KLD + kc + tg]);
                bK[1] = __float_as_uint(Ks[n * KLD + kc + tg + 4]);
                mma_tf32(S[ni], aQ[kk], bK);
            }
        }

        // ---- Online softmax in registers (log2 domain) ----
        float ym0 = -1e30f, ym1 = -1e30f;
#pragma unroll
        for (int ni = 0; ni < 8; ni++) {
            ym0 = fmaxf(ym0, fmaxf(S[ni][0], S[ni][1]));
            ym1 = fmaxf(ym1, fmaxf(S[ni][2], S[ni][3]));
        }
        ym0 = fmaxf(ym0, __shfl_xor_sync(0xffffffffu, ym0, 1));
        ym0 = fmaxf(ym0, __shfl_xor_sync(0xffffffffu, ym0, 2));
        ym1 = fmaxf(ym1, __shfl_xor_sync(0xffffffffu, ym1, 1));
        ym1 = fmaxf(ym1, __shfl_xor_sync(0xffffffffu, ym1, 2));
        float mn0 = fmaxf(m0, ym0 * cscale);
        float mn1 = fmaxf(m1, ym1 * cscale);
        float al0 = fexp2(m0 - mn0);
        float al1 = fexp2(m1 - mn1);

        float ls0 = 0.f, ls1 = 0.f;
        int r0 = wrow + g;
#pragma unroll
        for (int ni = 0; ni < 8; ni++) {
            float p0 = to_tf32(fexp2(fmaf(S[ni][0], cscale, -mn0)));
            float p1 = to_tf32(fexp2(fmaf(S[ni][1], cscale, -mn0)));
            float p2 = to_tf32(fexp2(fmaf(S[ni][2], cscale, -mn1)));
            float p3 = to_tf32(fexp2(fmaf(S[ni][3], cscale, -mn1)));
            ls0 += p0 + p1;
            ls1 += p2 + p3;
            int col = ni * 8 + tg * 2;
            *reinterpret_cast<float2*>(&Ps[r0 * PLD + col]) = make_float2(p0, p1);
            *reinterpret_cast<float2*>(&Ps[(r0 + 8) * PLD + col]) = make_float2(p2, p3);
        }
        ls0 += __shfl_xor_sync(0xffffffffu, ls0, 1);
        ls0 += __shfl_xor_sync(0xffffffffu, ls0, 2);
        ls1 += __shfl_xor_sync(0xffffffffu, ls1, 1);
        ls1 += __shfl_xor_sync(0xffffffffu, ls1, 2);

        l0 = l0 * al0 + ls0;
        l1 = l1 * al1 + ls1;
        m0 = mn0;
        m1 = mn1;
#pragma unroll
        for (int ni = 0; ni < 8; ni++) {
            O[ni][0] *= al0; O[ni][1] *= al0;
            O[ni][2] *= al1; O[ni][3] *= al1;
        }
        __syncwarp();

        // ---- O += P V (warp: 16 x 64) ----
#pragma unroll
        for (int kk = 0; kk < 8; kk++) {
            int kc = kk * 8;
            uint32_t aP[4];
            aP[0] = __float_as_uint(Ps[r0 * PLD + kc + tg]);
            aP[1] = __float_as_uint(Ps[(r0 + 8) * PLD + kc + tg]);
            aP[2] = __float_as_uint(Ps[r0 * PLD + kc + tg + 4]);
            aP[3] = __float_as_uint(Ps[(r0 + 8) * PLD + kc + tg + 4]);
#pragma unroll
            for (int ni = 0; ni < 8; ni++) {
                uint32_t bV[2];
                int n = ni * 8 + g;
                bV[0] = __float_as_uint(Vs[(kc + tg) * VLD + n]);
                bV[1] = __float_as_uint(Vs[(kc + tg + 4) * VLD + n]);
                mma_tf32(O[ni], aP, bV);
            }
        }
        __syncthreads();   // all warps done with Ks/Vs before next STS
    }

    // ---- Epilogue ----
    float inv0 = 1.0f / l0;
    float inv1 = 1.0f / l1;
    int row0 = qBase + wrow + g;
#pragma unroll
    for (int ni = 0; ni < 8; ni++) {
        int col = h * DHH + ni * 8 + tg * 2;
        float2 o0 = make_float2(O[ni][0] * inv0, O[ni][1] * inv0);
        float2 o1 = make_float2(O[ni][2] * inv1, O[ni][3] * inv1);
        *reinterpret_cast<float2*>(ctx + ((size_t)(b * NN + row0)) * DD + col) = o0;
        *reinterpret_cast<float2*>(ctx + ((size_t)(b * NN + row0 + 8)) * DD + col) = o1;
    }
}

// ---------------------------------------------------------------------------
// Launch
// ---------------------------------------------------------------------------
extern "C" void kernel_launch(void* const* d_in, const int* in_sizes, int n_in,
                              void* d_out, int out_size) {
    const float* x  = (const float*)d_in[0];
    const float* Wq = (const float*)d_in[1];
    const float* bq = (const float*)d_in[2];
    const float* Wk = (const float*)d_in[3];
    const float* bk = (const float*)d_in[4];
    const float* Wv = (const float*)d_in[5];
    const float* bv = (const float*)d_in[6];
    const float* Wo = (const float*)d_in[7];
    const float* bo = (const float*)d_in[8];
    float* out = (float*)d_out;

    float *qp, *kp, *vp, *cp;
    cudaGetSymbolAddress((void**)&qp, g_q);
    cudaGetSymbolAddress((void**)&kp, g_k);
    cudaGetSymbolAddress((void**)&vp, g_v);
    cudaGetSymbolAddress((void**)&cp, g_ctx);

    dim3 qkvGrid(DD / GBN, M_TOTAL / GBM, 3);   // (8, 32, 3)
    gemm_qkv_kernel<<<qkvGrid, 256>>>(x, Wq, Wk, Wv, bq, bk, bv, qp, kp, vp);

    cudaFuncSetAttribute(attn_mma_kernel,
                         cudaFuncAttributeMaxDynamicSharedMemorySize, ATTN_SMEM);
    dim3 attnGrid(BB * HH, NN / 128);           // (32, 16)
    attn_mma_kernel<<<attnGrid, 256, ATTN_SMEM>>>(qp, kp, vp, cp);

    dim3 gemmGrid(DD / GBN, M_TOTAL / GBM);     // (8, 32)
    gemm_mma_kernel<<<gemmGrid, 256>>>(cp, Wo, bo, out, M_TOTAL, DD, DD);
}

// round 7
// speedup vs baseline: 3.8487x; 1.1208x over previous
#include <cuda_runtime.h>
#include <math.h>
#include <stdint.h>

#define BB 2
#define NN 2048
#define DD 1024
#define HH 16
#define DHH 64
#define M_TOTAL (BB * NN)   // 4096

// Scratch (allocation-free rule: __device__ globals)
__device__ float g_q[M_TOTAL * DD];
__device__ float g_k[M_TOTAL * DD];
__device__ float g_v[M_TOTAL * DD];
__device__ float g_ctx[M_TOTAL * DD];
__device__ float g_xr[M_TOTAL * DD];    // tf32-rounded x
__device__ float g_wr[4 * DD * DD];     // tf32-rounded Wq,Wk,Wv,Wo

// ---------------------------------------------------------------------------
// Helpers
// ---------------------------------------------------------------------------
__device__ __forceinline__ float to_tf32(float x) {
    float r;
    asm("cvt.rna.tf32.f32 %0, %1;" : "=f"(r) : "f"(x));
    return r;
}

__device__ __forceinline__ uint32_t smem_u32(const void* p) {
    uint32_t a;
    asm("{ .reg .u64 t; cvta.to.shared.u64 t, %1; cvt.u32.u64 %0, t; }"
        : "=r"(a) : "l"(p));
    return a;
}

__device__ __forceinline__ void cp16(uint32_t s, const void* g) {
    asm volatile("cp.async.cg.shared.global [%0], [%1], 16;"
                 :: "r"(s), "l"(g));
}
__device__ __forceinline__ void cp_commit() {
    asm volatile("cp.async.commit_group;");
}
template <int N>
__device__ __forceinline__ void cp_wait() {
    asm volatile("cp.async.wait_group %0;" :: "n"(N));
}

__device__ __forceinline__ void mma_tf32(float* c, const uint32_t* a,
                                         const uint32_t* b) {
    asm volatile(
        "mma.sync.aligned.m16n8k8.row.col.f32.tf32.tf32.f32 "
        "{%0,%1,%2,%3}, {%4,%5,%6,%7}, {%8,%9}, {%0,%1,%2,%3};"
        : "+f"(c[0]), "+f"(c[1]), "+f"(c[2]), "+f"(c[3])
        : "r"(a[0]), "r"(a[1]), "r"(a[2]), "r"(a[3]), "r"(b[0]), "r"(b[1]));
}

// exp2 on the FMA/ALU pipes (no MUFU). |rel err| < 6e-5 for f in [-.5,.5].
__device__ __forceinline__ float fexp2(float y) {
    y = fmaxf(y, -120.0f);
    float t = y + 12582912.0f;
    int i = __float_as_int(t) - 0x4B400000;
    float f = y - (t - 12582912.0f);
    float p = 1.0f + f * (0.6931472f + f * (0.24022651f +
              f * (0.05550411f + f * 0.00961813f)));
    return __uint_as_float(__float_as_uint(p) + (i << 23));
}

// ---------------------------------------------------------------------------
// Pre-round x and the 4 weights to tf32 (once).
// grid: (4096, 5); y=0 -> x (1M float4), y=1..4 -> W's (256K float4 each)
// ---------------------------------------------------------------------------
__global__ __launch_bounds__(256)
void round_tf32_kernel(const float* __restrict__ x,
                       const float* __restrict__ Wq, const float* __restrict__ Wk,
                       const float* __restrict__ Wv, const float* __restrict__ Wo,
                       float* __restrict__ xr, float* __restrict__ wr) {
    int z = blockIdx.y;
    int i = blockIdx.x * 256 + threadIdx.x;
    const float* src;
    float* dst;
    int n4;
    if (z == 0) { src = x; dst = xr; n4 = M_TOTAL * DD / 4; }
    else {
        src = (z == 1) ? Wq : (z == 2) ? Wk : (z == 3) ? Wv : Wo;
        dst = wr + (size_t)(z - 1) * DD * DD;
        n4 = DD * DD / 4;
    }
    if (i < n4) {
        float4 v = reinterpret_cast<const float4*>(src)[i];
        v.x = to_tf32(v.x); v.y = to_tf32(v.y);
        v.z = to_tf32(v.z); v.w = to_tf32(v.w);
        reinterpret_cast<float4*>(dst)[i] = v;
    }
}

// ---------------------------------------------------------------------------
// cp.async double-buffered tf32 GEMM: Y = X @ W^T + bias.
// X, W already tf32-rounded. CTA tile 128x128, K-chunk 32, 8 warps.
// ROUND: round the output to tf32 (for q/k/v feeding attention).
// ---------------------------------------------------------------------------
#define GBM 128
#define GBN 128
#define GBK 32
#define GLD 36
#define GAB (GBM * GLD)                 // floats per A (or B) stage buffer
#define GEMM_SMEM (4 * GAB * 4)         // 73728 B

template <bool ROUND>
__device__ __forceinline__
void gemm_cp_body(const float* __restrict__ X, const float* __restrict__ W,
                  const float* __restrict__ bias, float* __restrict__ Y,
                  int Nd, int K) {
    extern __shared__ float sm[];

    const int tid = threadIdx.x;
    const int wid = tid >> 5;
    const int lane = tid & 31;
    const int g = lane >> 2;
    const int tg = lane & 3;
    const int wm = wid & 1;
    const int wn = wid >> 1;

    const int rowBase = blockIdx.y * GBM;
    const int colBase = blockIdx.x * GBN;

    const uint32_t base = smem_u32(sm);
    // layout: [A0 | B0 | A1 | B1]
    const int lrow = tid >> 3;           // 0..31 (row step 32 per p)
    const int lc4 = tid & 7;
    const uint32_t loff = (uint32_t)(lrow * GLD + lc4 * 4) * 4u;

    float c[4][4][4];
#pragma unroll
    for (int mi = 0; mi < 4; mi++)
#pragma unroll
        for (int ni = 0; ni < 4; ni++)
#pragma unroll
            for (int r = 0; r < 4; r++) c[mi][ni][r] = 0.f;

    const int nstages = K / GBK;

    // prologue: stage 0 -> buf 0
    {
        const float* xa = X + (size_t)(rowBase + lrow) * K + lc4 * 4;
        const float* wb = W + (size_t)(colBase + lrow) * K + lc4 * 4;
#pragma unroll
        for (int p = 0; p < 4; p++) {
            cp16(base + loff + p * 32 * GLD * 4, xa + (size_t)p * 32 * K);
            cp16(base + GAB * 4 + loff + p * 32 * GLD * 4, wb + (size_t)p * 32 * K);
        }
        cp_commit();
    }

    for (int i = 0; i < nstages; i++) {
        const int cur = i & 1;
        if (i + 1 < nstages) {
            const int k0 = (i + 1) * GBK;
            const uint32_t bufb = base + (cur ^ 1) * 2 * GAB * 4;
            const float* xa = X + (size_t)(rowBase + lrow) * K + k0 + lc4 * 4;
            const float* wb = W + (size_t)(colBase + lrow) * K + k0 + lc4 * 4;
#pragma unroll
            for (int p = 0; p < 4; p++) {
                cp16(bufb + loff + p * 32 * GLD * 4, xa + (size_t)p * 32 * K);
                cp16(bufb + GAB * 4 + loff + p * 32 * GLD * 4, wb + (size_t)p * 32 * K);
            }
            cp_commit();
            cp_wait<1>();
        } else {
            cp_wait<0>();
        }
        __syncthreads();

        const float* As = sm + cur * 2 * GAB;
        const float* Bs = As + GAB;
#pragma unroll
        for (int kk = 0; kk < GBK / 8; kk++) {
            uint32_t afrag[4][4];
            uint32_t bfrag[4][2];
            const int kc = kk * 8;
#pragma unroll
            for (int mi = 0; mi < 4; mi++) {
                int r = wm * 64 + mi * 16 + g;
                afrag[mi][0] = __float_as_uint(As[r * GLD + kc + tg]);
                afrag[mi][1] = __float_as_uint(As[(r + 8) * GLD + kc + tg]);
                afrag[mi][2] = __float_as_uint(As[r * GLD + kc + tg + 4]);
                afrag[mi][3] = __float_as_uint(As[(r + 8) * GLD + kc + tg + 4]);
            }
#pragma unroll
            for (int ni = 0; ni < 4; ni++) {
                int n = wn * 32 + ni * 8 + g;
                bfrag[ni][0] = __float_as_uint(Bs[n * GLD + kc + tg]);
                bfrag[ni][1] = __float_as_uint(Bs[n * GLD + kc + tg + 4]);
            }
#pragma unroll
            for (int mi = 0; mi < 4; mi++)
#pragma unroll
                for (int ni = 0; ni < 4; ni++)
                    mma_tf32(c[mi][ni], afrag[mi], bfrag[ni]);
        }
        __syncthreads();
    }

#pragma unroll
    for (int mi = 0; mi < 4; mi++) {
        int row0 = rowBase + wm * 64 + mi * 16 + g;
#pragma unroll
        for (int ni = 0; ni < 4; ni++) {
            int col = colBase + wn * 32 + ni * 8 + tg * 2;
            float2 bv = *reinterpret_cast<const float2*>(bias + col);
            float2 o0, o1;
            if (ROUND) {
                o0.x = to_tf32(c[mi][ni][0] + bv.x);
                o0.y = to_tf32(c[mi][ni][1] + bv.y);
                o1.x = to_tf32(c[mi][ni][2] + bv.x);
                o1.y = to_tf32(c[mi][ni][3] + bv.y);
            } else {
                o0.x = c[mi][ni][0] + bv.x;
                o0.y = c[mi][ni][1] + bv.y;
                o1.x = c[mi][ni][2] + bv.x;
                o1.y = c[mi][ni][3] + bv.y;
            }
            *reinterpret_cast<float2*>(Y + (size_t)row0 * Nd + col) = o0;
            *reinterpret_cast<float2*>(Y + (size_t)(row0 + 8) * Nd + col) = o1;
        }
    }
}

// Fused Q/K/V projection (z selects), X/W pre-rounded, outputs rounded.
__global__ __launch_bounds__(256, 2)
void gemm_qkv_kernel(const float* __restrict__ Xr, const float* __restrict__ Wr,
                     const float* __restrict__ bq, const float* __restrict__ bk,
                     const float* __restrict__ bv,
                     float* __restrict__ q, float* __restrict__ kk,
                     float* __restrict__ vv) {
    const int z = blockIdx.z;
    const float* W = Wr + (size_t)z * DD * DD;
    const float* bias = (z == 0) ? bq : (z == 1) ? bk : bv;
    float* Y = (z == 0) ? q : (z == 1) ? kk : vv;
    gemm_cp_body<true>(Xr, W, bias, Y, DD, DD);
}

// Output projection: ctx (pre-rounded) @ Wo^T + bo, full fp32 out.
__global__ __launch_bounds__(256, 2)
void gemm_o_kernel(const float* __restrict__ ctx, const float* __restrict__ Wor,
                   const float* __restrict__ bo, float* __restrict__ out) {
    gemm_cp_body<false>(ctx, Wor, bo, out, DD, DD);
}

// ---------------------------------------------------------------------------
// Tensor-core flash attention v3: cp.async double-buffered K/V.
// Block: 256 threads = 8 warps; qtile 128 (16 rows/warp); ktile 64.
// Inputs q/k/v already tf32-rounded. ctx written tf32-rounded.
// smem: Ps[128][68] | K0[64][68] | V0[64][72] | K1 | V1 = 104 KB.
// ---------------------------------------------------------------------------
#define PLD 68
#define KLD 68
#define VLD 72
#define PS_F (128 * PLD)            // 8704 floats
#define KS_F (64 * KLD)             // 4352
#define VS_F (64 * VLD)             // 4608
#define ATTN_SMEM ((PS_F + 2 * (KS_F + VS_F)) * 4)   // 106496 B

__global__ __launch_bounds__(256, 2)
void attn_mma_kernel(const float* __restrict__ q, const float* __restrict__ k,
                     const float* __restrict__ v, float* __restrict__ ctx) {
    extern __shared__ float smf[];
    float* Ps = smf;

    const int tid = threadIdx.x;
    const int wid = tid >> 5;
    const int lane = tid & 31;
    const int g = lane >> 2;
    const int tg = lane & 3;
    const int wrow = wid * 16;

    const int bh = blockIdx.x;
    const int b = bh / HH;
    const int h = bh % HH;
    const int qBase = blockIdx.y * 128;

    const float cscale = 0.18033688f;   // (1/8) * log2(e)

    const float* kbase = k + ((size_t)(b * NN)) * DD + h * DHH;
    const float* vbase = v + ((size_t)(b * NN)) * DD + h * DHH;

    const uint32_t base = smem_u32(smf);
    const uint32_t kvbase[2] = { base + PS_F * 4,
                                 base + (PS_F + KS_F + VS_F) * 4 };

    // K/V cp.async mapping: 64 rows x 16 chunks; 4 chunks/thread/tensor
    const int lrow = tid >> 4;          // 0..15 (+16 per p)
    const int lc4 = tid & 15;

    // ---- Issue tile 0 ----
    {
        const float* kp = kbase + (size_t)lrow * DD + lc4 * 4;
        const float* vp = vbase + (size_t)lrow * DD + lc4 * 4;
#pragma unroll
        for (int p = 0; p < 4; p++) {
            uint32_t ro = (uint32_t)((lrow + p * 16) * KLD + lc4 * 4) * 4u;
            uint32_t rv = (uint32_t)((lrow + p * 16) * VLD + lc4 * 4) * 4u;
            cp16(kvbase[0] + ro, kp + (size_t)p * 16 * DD);
            cp16(kvbase[0] + KS_F * 4 + rv, vp + (size_t)p * 16 * DD);
        }
        cp_commit();
    }

    // ---- Load Q tile (128 x 64) into Ps (already tf32) ----
    {
        const float* qsrc = q + ((size_t)(b * NN + qBase)) * DD + h * DHH;
#pragma unroll
        for (int p = 0; p < 8; p++) {
            int idx = p * 256 + tid;
            int row = idx >> 4;
            int c4 = idx & 15;
            float4 a = *reinterpret_cast<const float4*>(qsrc + (size_t)row * DD + c4 * 4);
            *reinterpret_cast<float4*>(&Ps[row * PLD + c4 * 4]) = a;
        }
    }
    __syncthreads();

    // ---- Q fragments -> registers ----
    uint32_t aQ[8][4];
#pragma unroll
    for (int kk = 0; kk < 8; kk++) {
        int kc = kk * 8;
        int r = wrow + g;
        aQ[kk][0] = __float_as_uint(Ps[r * PLD + kc + tg]);
        aQ[kk][1] = __float_as_uint(Ps[(r + 8) * PLD + kc + tg]);
        aQ[kk][2] = __float_as_uint(Ps[r * PLD + kc + tg + 4]);
        aQ[kk][3] = __float_as_uint(Ps[(r + 8) * PLD + kc + tg + 4]);
    }

    float m0 = -1e30f, m1 = -1e30f, l0 = 0.f, l1 = 0.f;
    float O[8][4];
#pragma unroll
    for (int ni = 0; ni < 8; ni++)
#pragma unroll
        for (int r = 0; r < 4; r++) O[ni][r] = 0.f;

    const int ntiles = NN / 64;
    for (int i = 0; i < ntiles; i++) {
        const int cur = i & 1;

        if (i + 1 < ntiles) {
            const float* kp = kbase + (size_t)((i + 1) * 64 + lrow) * DD + lc4 * 4;
            const float* vp = vbase + (size_t)((i + 1) * 64 + lrow) * DD + lc4 * 4;
            const uint32_t dst = kvbase[cur ^ 1];
#pragma unroll
            for (int p = 0; p < 4; p++) {
                uint32_t ro = (uint32_t)((lrow + p * 16) * KLD + lc4 * 4) * 4u;
                uint32_t rv = (uint32_t)((lrow + p * 16) * VLD + lc4 * 4) * 4u;
                cp16(dst + ro, kp + (size_t)p * 16 * DD);
                cp16(dst + KS_F * 4 + rv, vp + (size_t)p * 16 * DD);
            }
            cp_commit();
            cp_wait<1>();
        } else {
            cp_wait<0>();
        }
        __syncthreads();

        const float* Ks = smf + PS_F + cur * (KS_F + VS_F);
        const float* Vs = Ks + KS_F;

        // ---- S = Q K^T ----
        float S[8][4];
#pragma unroll
        for (int ni = 0; ni < 8; ni++)
#pragma unroll
            for (int r = 0; r < 4; r++) S[ni][r] = 0.f;
#pragma unroll
        for (int kk = 0; kk < 8; kk++) {
            int kc = kk * 8;
#pragma unroll
            for (int ni = 0; ni < 8; ni++) {
                uint32_t bK[2];
                int n = ni * 8 + g;
                bK[0] = __float_as_uint(Ks[n * KLD + kc + tg]);
                bK[1] = __float_as_uint(Ks[n * KLD + kc + tg + 4]);
                mma_tf32(S[ni], aQ[kk], bK);
            }
        }

        // ---- Online softmax (log2 domain) ----
        float ym0 = -1e30f, ym1 = -1e30f;
#pragma unroll
        for (int ni = 0; ni < 8; ni++) {
            ym0 = fmaxf(ym0, fmaxf(S[ni][0], S[ni][1]));
            ym1 = fmaxf(ym1, fmaxf(S[ni][2], S[ni][3]));
        }
        ym0 = fmaxf(ym0, __shfl_xor_sync(0xffffffffu, ym0, 1));
        ym0 = fmaxf(ym0, __shfl_xor_sync(0xffffffffu, ym0, 2));
        ym1 = fmaxf(ym1, __shfl_xor_sync(0xffffffffu, ym1, 1));
        ym1 = fmaxf(ym1, __shfl_xor_sync(0xffffffffu, ym1, 2));
        float mn0 = fmaxf(m0, ym0 * cscale);
        float mn1 = fmaxf(m1, ym1 * cscale);
        float al0 = fexp2(m0 - mn0);
        float al1 = fexp2(m1 - mn1);

        float ls0 = 0.f, ls1 = 0.f;
        int r0 = wrow + g;
#pragma unroll
        for (int ni = 0; ni < 8; ni++) {
            float p0 = to_tf32(fexp2(fmaf(S[ni][0], cscale, -mn0)));
            float p1 = to_tf32(fexp2(fmaf(S[ni][1], cscale, -mn0)));
            float p2 = to_tf32(fexp2(fmaf(S[ni][2], cscale, -mn1)));
            float p3 = to_tf32(fexp2(fmaf(S[ni][3], cscale, -mn1)));
            ls0 += p0 + p1;
            ls1 += p2 + p3;
            int col = ni * 8 + tg * 2;
            *reinterpret_cast<float2*>(&Ps[r0 * PLD + col]) = make_float2(p0, p1);
            *reinterpret_cast<float2*>(&Ps[(r0 + 8) * PLD + col]) = make_float2(p2, p3);
        }
        ls0 += __shfl_xor_sync(0xffffffffu, ls0, 1);
        ls0 += __shfl_xor_sync(0xffffffffu, ls0, 2);
        ls1 += __shfl_xor_sync(0xffffffffu, ls1, 1);
        ls1 += __shfl_xor_sync(0xffffffffu, ls1, 2);

        l0 = l0 * al0 + ls0;
        l1 = l1 * al1 + ls1;
        m0 = mn0;
        m1 = mn1;
#pragma unroll
        for (int ni = 0; ni < 8; ni++) {
            O[ni][0] *= al0; O[ni][1] *= al0;
            O[ni][2] *= al1; O[ni][3] *= al1;
        }
        __syncwarp();

        // ---- O += P V ----
#pragma unroll
        for (int kk = 0; kk < 8; kk++) {
            int kc = kk * 8;
            uint32_t aP[4];
            aP[0] = __float_as_uint(Ps[r0 * PLD + kc + tg]);
            aP[1] = __float_as_uint(Ps[(r0 + 8) * PLD + kc + tg]);
            aP[2] = __float_as_uint(Ps[r0 * PLD + kc + tg + 4]);
            aP[3] = __float_as_uint(Ps[(r0 + 8) * PLD + kc + tg + 4]);
#pragma unroll
            for (int ni = 0; ni < 8; ni++) {
                uint32_t bV[2];
                int n = ni * 8 + g;
                bV[0] = __float_as_uint(Vs[(kc + tg) * VLD + n]);
                bV[1] = __float_as_uint(Vs[(kc + tg + 4) * VLD + n]);
                mma_tf32(O[ni], aP, bV);
            }
        }
        __syncthreads();   // K/V[cur] reads done before next issue overwrites
    }

    // ---- Epilogue: write tf32-rounded ctx (feeds O-projection GEMM) ----
    float inv0 = 1.0f / l0;
    float inv1 = 1.0f / l1;
    int row0 = qBase + wrow + g;
#pragma unroll
    for (int ni = 0; ni < 8; ni++) {
        int col = h * DHH + ni * 8 + tg * 2;
        float2 o0 = make_float2(to_tf32(O[ni][0] * inv0), to_tf32(O[ni][1] * inv0));
        float2 o1 = make_float2(to_tf32(O[ni][2] * inv1), to_tf32(O[ni][3] * inv1));
        *reinterpret_cast<float2*>(ctx + ((size_t)(b * NN + row0)) * DD + col) = o0;
        *reinterpret_cast<float2*>(ctx + ((size_t)(b * NN + row0 + 8)) * DD + col) = o1;
    }
}

// ---------------------------------------------------------------------------
// Launch
// ---------------------------------------------------------------------------
extern "C" void kernel_launch(void* const* d_in, const int* in_sizes, int n_in,
                              void* d_out, int out_size) {
    const float* x  = (const float*)d_in[0];
    const float* Wq = (const float*)d_in[1];
    const float* bq = (const float*)d_in[2];
    const float* Wk = (const float*)d_in[3];
    const float* bk = (const float*)d_in[4];
    const float* Wv = (const float*)d_in[5];
    const float* bv = (const float*)d_in[6];
    const float* Wo = (const float*)d_in[7];
    const float* bo = (const float*)d_in[8];
    float* out = (float*)d_out;

    float *qp, *kp, *vp, *cp, *xrp, *wrp;
    cudaGetSymbolAddress((void**)&qp, g_q);
    cudaGetSymbolAddress((void**)&kp, g_k);
    cudaGetSymbolAddress((void**)&vp, g_v);
    cudaGetSymbolAddress((void**)&cp, g_ctx);
    cudaGetSymbolAddress((void**)&xrp, g_xr);
    cudaGetSymbolAddress((void**)&wrp, g_wr);

    cudaFuncSetAttribute(gemm_qkv_kernel,
                         cudaFuncAttributeMaxDynamicSharedMemorySize, GEMM_SMEM);
    cudaFuncSetAttribute(gemm_o_kernel,
                         cudaFuncAttributeMaxDynamicSharedMemorySize, GEMM_SMEM);
    cudaFuncSetAttribute(attn_mma_kernel,
                         cudaFuncAttributeMaxDynamicSharedMemorySize, ATTN_SMEM);

    dim3 roundGrid(M_TOTAL * DD / 4 / 256, 5);   // (4096, 5)
    round_tf32_kernel<<<roundGrid, 256>>>(x, Wq, Wk, Wv, Wo, xrp, wrp);

    dim3 qkvGrid(DD / GBN, M_TOTAL / GBM, 3);    // (8, 32, 3)
    gemm_qkv_kernel<<<qkvGrid, 256, GEMM_SMEM>>>(xrp, wrp, bq, bk, bv, qp, kp, vp);

    dim3 attnGrid(BB * HH, NN / 128);            // (32, 16)
    attn_mma_kernel<<<attnGrid, 256, ATTN_SMEM>>>(qp, kp, vp, cp);

    dim3 gemmGrid(DD / GBN, M_TOTAL / GBM);      // (8, 32)
    gemm_o_kernel<<<gemmGrid, 256, GEMM_SMEM>>>(cp, wrp + (size_t)3 * DD * DD, bo, out);
}

// round 8
// speedup vs baseline: 4.1041x; 1.0664x over previous
#include <cuda_runtime.h>
#include <math.h>
#include <stdint.h>

#define BB 2
#define NN 2048
#define DD 1024
#define HH 16
#define DHH 64
#define M_TOTAL (BB * NN)   // 4096

// Scratch (allocation-free rule: __device__ globals)
__device__ float g_q[M_TOTAL * DD];
__device__ float g_k[M_TOTAL * DD];
__device__ float g_v[M_TOTAL * DD];
__device__ float g_ctx[M_TOTAL * DD];
__device__ float g_xr[M_TOTAL * DD];    // tf32-rounded x
__device__ float g_wr[4 * DD * DD];     // tf32-rounded Wq,Wk,Wv,Wo

// ---------------------------------------------------------------------------
// Helpers
// ---------------------------------------------------------------------------
__device__ __forceinline__ float to_tf32(float x) {
    float r;
    asm("cvt.rna.tf32.f32 %0, %1;" : "=f"(r) : "f"(x));
    return r;
}

__device__ __forceinline__ uint32_t smem_u32(const void* p) {
    uint32_t a;
    asm("{ .reg .u64 t; cvta.to.shared.u64 t, %1; cvt.u32.u64 %0, t; }"
        : "=r"(a) : "l"(p));
    return a;
}

__device__ __forceinline__ void cp16(uint32_t s, const void* g) {
    asm volatile("cp.async.cg.shared.global [%0], [%1], 16;"
                 :: "r"(s), "l"(g));
}
__device__ __forceinline__ void cp_commit() {
    asm volatile("cp.async.commit_group;");
}
template <int N>
__device__ __forceinline__ void cp_wait() {
    asm volatile("cp.async.wait_group %0;" :: "n"(N));
}

__device__ __forceinline__ void mma_tf32(float* c, const uint32_t* a,
                                         const uint32_t* b) {
    asm volatile(
        "mma.sync.aligned.m16n8k8.row.col.f32.tf32.tf32.f32 "
        "{%0,%1,%2,%3}, {%4,%5,%6,%7}, {%8,%9}, {%0,%1,%2,%3};"
        : "+f"(c[0]), "+f"(c[1]), "+f"(c[2]), "+f"(c[3])
        : "r"(a[0]), "r"(a[1]), "r"(a[2]), "r"(a[3]), "r"(b[0]), "r"(b[1]));
}

// ldmatrix: 4x (8x8 b32-as-8x16-b16) tiles -> 4 regs; lane l feeds matrix l/8.
__device__ __forceinline__ void ldsm_x4(uint32_t& r0, uint32_t& r1,
                                        uint32_t& r2, uint32_t& r3,
                                        uint32_t addr) {
    asm volatile("ldmatrix.sync.aligned.m8n8.x4.shared.b16 {%0,%1,%2,%3}, [%4];"
                 : "=r"(r0), "=r"(r1), "=r"(r2), "=r"(r3) : "r"(addr));
}

// exp2 on the FMA/ALU pipes (no MUFU). |rel err| < 6e-5 for f in [-.5,.5].
__device__ __forceinline__ float fexp2(float y) {
    y = fmaxf(y, -120.0f);
    float t = y + 12582912.0f;
    int i = __float_as_int(t) - 0x4B400000;
    float f = y - (t - 12582912.0f);
    float p = 1.0f + f * (0.6931472f + f * (0.24022651f +
              f * (0.05550411f + f * 0.00961813f)));
    return __uint_as_float(__float_as_uint(p) + (i << 23));
}

// ---------------------------------------------------------------------------
// Pre-round x and the 4 weights to tf32 (once).
// ---------------------------------------------------------------------------
__global__ __launch_bounds__(256)
void round_tf32_kernel(const float* __restrict__ x,
                       const float* __restrict__ Wq, const float* __restrict__ Wk,
                       const float* __restrict__ Wv, const float* __restrict__ Wo,
                       float* __restrict__ xr, float* __restrict__ wr) {
    int z = blockIdx.y;
    int i = blockIdx.x * 256 + threadIdx.x;
    const float* src;
    float* dst;
    int n4;
    if (z == 0) { src = x; dst = xr; n4 = M_TOTAL * DD / 4; }
    else {
        src = (z == 1) ? Wq : (z == 2) ? Wk : (z == 3) ? Wv : Wo;
        dst = wr + (size_t)(z - 1) * DD * DD;
        n4 = DD * DD / 4;
    }
    if (i < n4) {
        float4 v = reinterpret_cast<const float4*>(src)[i];
        v.x = to_tf32(v.x); v.y = to_tf32(v.y);
        v.z = to_tf32(v.z); v.w = to_tf32(v.w);
        reinterpret_cast<float4*>(dst)[i] = v;
    }
}

// ---------------------------------------------------------------------------
// 3-stage cp.async tf32 GEMM with ldmatrix fragment loads.
// Y = X @ W^T + bias. CTA tile 128x128, K-chunk 32, 8 warps.
// ---------------------------------------------------------------------------
#define GBM 128
#define GBN 128
#define GBK 32
#define GLD 36
#define GAB (GBM * GLD)                 // floats per A (or B) stage buffer
#define GSTAGE (2 * GAB * 4)            // bytes per stage (A+B)
#define GEMM_SMEM (3 * GSTAGE)          // 110592 B

template <bool ROUND>
__device__ __forceinline__
void gemm_cp_body(const float* __restrict__ X, const float* __restrict__ W,
                  const float* __restrict__ bias, float* __restrict__ Y,
                  int Nd, int K) {
    extern __shared__ float sm[];

    const int tid = threadIdx.x;
    const int wid = tid >> 5;
    const int lane = tid & 31;
    const int g = lane >> 2;
    const int tg = lane & 3;
    const int wm = wid & 1;
    const int wn = wid >> 1;

    const int rowBase = blockIdx.y * GBM;
    const int colBase = blockIdx.x * GBN;

    const uint32_t base = smem_u32(sm);

    // cp.async mapping: 32 rows x 8 chunks, 4 row-steps
    const int lrow = tid >> 3;
    const int lc4 = tid & 7;
    const uint32_t loff = (uint32_t)(lrow * GLD + lc4 * 4) * 4u;

    // ldmatrix lane selectors
    const int a_rs = (lane & 7) + ((lane >> 3) & 1) * 8;   // A row select
    const int a_cs = (lane >> 4) * 4;                      // A col select
    const int b_rs = (lane & 7) + (lane >> 4) * 8;         // B row select
    const int b_cs = ((lane >> 3) & 1) * 4;                // B col select

    float c[4][4][4];
#pragma unroll
    for (int mi = 0; mi < 4; mi++)
#pragma unroll
        for (int ni = 0; ni < 4; ni++)
#pragma unroll
            for (int r = 0; r < 4; r++) c[mi][ni][r] = 0.f;

    const int nstages = K / GBK;

    auto issue = [&](int s) {
        const uint32_t buf = base + (uint32_t)(s % 3) * GSTAGE;
        const int k0 = s * GBK;
        const float* xa = X + (size_t)(rowBase + lrow) * K + k0 + lc4 * 4;
        const float* wb = W + (size_t)(colBase + lrow) * K + k0 + lc4 * 4;
#pragma unroll
        for (int p = 0; p < 4; p++) {
            cp16(buf + loff + p * 32 * GLD * 4, xa + (size_t)p * 32 * K);
            cp16(buf + GAB * 4 + loff + p * 32 * GLD * 4, wb + (size_t)p * 32 * K);
        }
        cp_commit();
    };

    issue(0);
    issue(1);

    for (int i = 0; i < nstages; i++) {
        if (i + 1 < nstages) cp_wait<1>();
        else cp_wait<0>();
        __syncthreads();
        if (i + 2 < nstages) issue(i + 2);

        const uint32_t aS = base + (uint32_t)(i % 3) * GSTAGE;
        const uint32_t bS = aS + GAB * 4;
#pragma unroll
        for (int kk = 0; kk < GBK / 8; kk++) {
            const int kc = kk * 8;
            uint32_t afrag[4][4];
            uint32_t bfrag[4][2];
#pragma unroll
            for (int mi = 0; mi < 4; mi++) {
                uint32_t addr = aS + (uint32_t)((wm * 64 + mi * 16 + a_rs) * GLD
                                                + kc + a_cs) * 4u;
                ldsm_x4(afrag[mi][0], afrag[mi][1], afrag[mi][2], afrag[mi][3], addr);
            }
#pragma unroll
            for (int p = 0; p < 2; p++) {
                uint32_t addr = bS + (uint32_t)((wn * 32 + p * 16 + b_rs) * GLD
                                                + kc + b_cs) * 4u;
                ldsm_x4(bfrag[2 * p][0], bfrag[2 * p][1],
                        bfrag[2 * p + 1][0], bfrag[2 * p + 1][1], addr);
            }
#pragma unroll
            for (int mi = 0; mi < 4; mi++)
#pragma unroll
                for (int ni = 0; ni < 4; ni++)
                    mma_tf32(c[mi][ni], afrag[mi], bfrag[ni]);
        }
    }

#pragma unroll
    for (int mi = 0; mi < 4; mi++) {
        int row0 = rowBase + wm * 64 + mi * 16 + g;
#pragma unroll
        for (int ni = 0; ni < 4; ni++) {
            int col = colBase + wn * 32 + ni * 8 + tg * 2;
            float2 bv = *reinterpret_cast<const float2*>(bias + col);
            float2 o0, o1;
            if (ROUND) {
                o0.x = to_tf32(c[mi][ni][0] + bv.x);
                o0.y = to_tf32(c[mi][ni][1] + bv.y);
                o1.x = to_tf32(c[mi][ni][2] + bv.x);
                o1.y = to_tf32(c[mi][ni][3] + bv.y);
            } else {
                o0.x = c[mi][ni][0] + bv.x;
                o0.y = c[mi][ni][1] + bv.y;
                o1.x = c[mi][ni][2] + bv.x;
                o1.y = c[mi][ni][3] + bv.y;
            }
            *reinterpret_cast<float2*>(Y + (size_t)row0 * Nd + col) = o0;
            *reinterpret_cast<float2*>(Y + (size_t)(row0 + 8) * Nd + col) = o1;
        }
    }
}

__global__ __launch_bounds__(256, 2)
void gemm_qkv_kernel(const float* __restrict__ Xr, const float* __restrict__ Wr,
                     const float* __restrict__ bq, const float* __restrict__ bk,
                     const float* __restrict__ bv,
                     float* __restrict__ q, float* __restrict__ kk,
                     float* __restrict__ vv) {
    const int z = blockIdx.z;
    const float* W = Wr + (size_t)z * DD * DD;
    const float* bias = (z == 0) ? bq : (z == 1) ? bk : bv;
    float* Y = (z == 0) ? q : (z == 1) ? kk : vv;
    gemm_cp_body<true>(Xr, W, bias, Y, DD, DD);
}

__global__ __launch_bounds__(256, 2)
void gemm_o_kernel(const float* __restrict__ ctx, const float* __restrict__ Wor,
                   const float* __restrict__ bo, float* __restrict__ out) {
    gemm_cp_body<false>(ctx, Wor, bo, out, DD, DD);
}

// ---------------------------------------------------------------------------
// Tensor-core flash attention v4: cp.async K/V double buffer + ldmatrix frags.
// Block: 256 threads = 8 warps; qtile 128; ktile 64.
// smem: Ps[128][68] | K0[64][68] | V0[64][72] | K1 | V1 = 104 KB.
// ---------------------------------------------------------------------------
#define PLD 68
#define KLD 68
#define VLD 72
#define PS_F (128 * PLD)
#define KS_F (64 * KLD)
#define VS_F (64 * VLD)
#define ATTN_SMEM ((PS_F + 2 * (KS_F + VS_F)) * 4)

__global__ __launch_bounds__(256, 2)
void attn_mma_kernel(const float* __restrict__ q, const float* __restrict__ k,
                     const float* __restrict__ v, float* __restrict__ ctx) {
    extern __shared__ float smf[];
    float* Ps = smf;

    const int tid = threadIdx.x;
    const int wid = tid >> 5;
    const int lane = tid & 31;
    const int g = lane >> 2;
    const int tg = lane & 3;
    const int wrow = wid * 16;

    const int bh = blockIdx.x;
    const int b = bh / HH;
    const int h = bh % HH;
    const int qBase = blockIdx.y * 128;

    const float cscale = 0.18033688f;   // (1/8) * log2(e)

    const float* kbase = k + ((size_t)(b * NN)) * DD + h * DHH;
    const float* vbase = v + ((size_t)(b * NN)) * DD + h * DHH;

    const uint32_t base = smem_u32(smf);
    const uint32_t kvbase[2] = { base + PS_F * 4,
                                 base + (PS_F + KS_F + VS_F) * 4 };

    const int lrow = tid >> 4;
    const int lc4 = tid & 15;

    // ldmatrix lane selectors
    const int a_rs = (lane & 7) + ((lane >> 3) & 1) * 8;
    const int a_cs = (lane >> 4) * 4;
    const int b_rs = (lane & 7) + (lane >> 4) * 8;
    const int b_cs = ((lane >> 3) & 1) * 4;

    // ---- Issue K/V tile 0 ----
    {
        const float* kp = kbase + (size_t)lrow * DD + lc4 * 4;
        const float* vp = vbase + (size_t)lrow * DD + lc4 * 4;
#pragma unroll
        for (int p = 0; p < 4; p++) {
            uint32_t ro = (uint32_t)((lrow + p * 16) * KLD + lc4 * 4) * 4u;
            uint32_t rv = (uint32_t)((lrow + p * 16) * VLD + lc4 * 4) * 4u;
            cp16(kvbase[0] + ro, kp + (size_t)p * 16 * DD);
            cp16(kvbase[0] + KS_F * 4 + rv, vp + (size_t)p * 16 * DD);
        }
        cp_commit();
    }

    // ---- Load Q tile (128 x 64) into Ps (already tf32) ----
    {
        const float* qsrc = q + ((size_t)(b * NN + qBase)) * DD + h * DHH;
#pragma unroll
        for (int p = 0; p < 8; p++) {
            int idx = p * 256 + tid;
            int row = idx >> 4;
            int c4 = idx & 15;
            float4 a = *reinterpret_cast<const float4*>(qsrc + (size_t)row * DD + c4 * 4);
            *reinterpret_cast<float4*>(&Ps[row * PLD + c4 * 4]) = a;
        }
    }
    __syncthreads();

    // ---- Q fragments -> registers (ldmatrix) ----
    uint32_t aQ[8][4];
#pragma unroll
    for (int kk = 0; kk < 8; kk++) {
        uint32_t addr = base + (uint32_t)((wrow + a_rs) * PLD + kk * 8 + a_cs) * 4u;
        ldsm_x4(aQ[kk][0], aQ[kk][1], aQ[kk][2], aQ[kk][3], addr);
    }

    float m0 = -1e30f, m1 = -1e30f, l0 = 0.f, l1 = 0.f;
    float O[8][4];
#pragma unroll
    for (int ni = 0; ni < 8; ni++)
#pragma unroll
        for (int r = 0; r < 4; r++) O[ni][r] = 0.f;

    const int ntiles = NN / 64;
    for (int i = 0; i < ntiles; i++) {
        const int cur = i & 1;

        if (i + 1 < ntiles) {
            const float* kp = kbase + (size_t)((i + 1) * 64 + lrow) * DD + lc4 * 4;
            const float* vp = vbase + (size_t)((i + 1) * 64 + lrow) * DD + lc4 * 4;
            const uint32_t dst = kvbase[cur ^ 1];
#pragma unroll
            for (int p = 0; p < 4; p++) {
                uint32_t ro = (uint32_t)((lrow + p * 16) * KLD + lc4 * 4) * 4u;
                uint32_t rv = (uint32_t)((lrow + p * 16) * VLD + lc4 * 4) * 4u;
                cp16(dst + ro, kp + (size_t)p * 16 * DD);
                cp16(dst + KS_F * 4 + rv, vp + (size_t)p * 16 * DD);
            }
            cp_commit();
            cp_wait<1>();
        } else {
            cp_wait<0>();
        }
        __syncthreads();

        const uint32_t ksU = kvbase[cur];
        const float* Vs = smf + PS_F + cur * (KS_F + VS_F) + KS_F;

        // ---- S = Q K^T (K B-frags via ldmatrix) ----
        float S[8][4];
#pragma unroll
        for (int ni = 0; ni < 8; ni++)
#pragma unroll
            for (int r = 0; r < 4; r++) S[ni][r] = 0.f;
#pragma unroll
        for (int kk = 0; kk < 8; kk++) {
            const int kc = kk * 8;
#pragma unroll
            for (int p = 0; p < 4; p++) {
                uint32_t bK[4];
                uint32_t addr = ksU + (uint32_t)((p * 16 + b_rs) * KLD + kc + b_cs) * 4u;
                ldsm_x4(bK[0], bK[1], bK[2], bK[3], addr);
                mma_tf32(S[2 * p], aQ[kk], bK);
                mma_tf32(S[2 * p + 1], aQ[kk], bK + 2);
            }
        }

        // ---- Online softmax (log2 domain) ----
        float ym0 = -1e30f, ym1 = -1e30f;
#pragma unroll
        for (int ni = 0; ni < 8; ni++) {
            ym0 = fmaxf(ym0, fmaxf(S[ni][0], S[ni][1]));
            ym1 = fmaxf(ym1, fmaxf(S[ni][2], S[ni][3]));
        }
        ym0 = fmaxf(ym0, __shfl_xor_sync(0xffffffffu, ym0, 1));
        ym0 = fmaxf(ym0, __shfl_xor_sync(0xffffffffu, ym0, 2));
        ym1 = fmaxf(ym1, __shfl_xor_sync(0xffffffffu, ym1, 1));
        ym1 = fmaxf(ym1, __shfl_xor_sync(0xffffffffu, ym1, 2));
        float mn0 = fmaxf(m0, ym0 * cscale);
        float mn1 = fmaxf(m1, ym1 * cscale);
        float al0 = fexp2(m0 - mn0);
        float al1 = fexp2(m1 - mn1);

        float ls0 = 0.f, ls1 = 0.f;
        int r0 = wrow + g;
#pragma unroll
        for (int ni = 0; ni < 8; ni++) {
            float p0 = to_tf32(fexp2(fmaf(S[ni][0], cscale, -mn0)));
            float p1 = to_tf32(fexp2(fmaf(S[ni][1], cscale, -mn0)));
            float p2 = to_tf32(fexp2(fmaf(S[ni][2], cscale, -mn1)));
            float p3 = to_tf32(fexp2(fmaf(S[ni][3], cscale, -mn1)));
            ls0 += p0 + p1;
            ls1 += p2 + p3;
            int col = ni * 8 + tg * 2;
            *reinterpret_cast<float2*>(&Ps[r0 * PLD + col]) = make_float2(p0, p1);
            *reinterpret_cast<float2*>(&Ps[(r0 + 8) * PLD + col]) = make_float2(p2, p3);
        }
        ls0 += __shfl_xor_sync(0xffffffffu, ls0, 1);
        ls0 += __shfl_xor_sync(0xffffffffu, ls0, 2);
        ls1 += __shfl_xor_sync(0xffffffffu, ls1, 1);
        ls1 += __shfl_xor_sync(0xffffffffu, ls1, 2);

        l0 = l0 * al0 + ls0;
        l1 = l1 * al1 + ls1;
        m0 = mn0;
        m1 = mn1;
#pragma unroll
        for (int ni = 0; ni < 8; ni++) {
            O[ni][0] *= al0; O[ni][1] *= al0;
            O[ni][2] *= al1; O[ni][3] *= al1;
        }
        __syncwarp();

        // ---- O += P V (P A-frags via ldmatrix; V scalar, conflict-free) ----
#pragma unroll
        for (int kk = 0; kk < 8; kk++) {
            const int kc = kk * 8;
            uint32_t aP[4];
            uint32_t addr = base + (uint32_t)((wrow + a_rs) * PLD + kc + a_cs) * 4u;
            ldsm_x4(aP[0], aP[1], aP[2], aP[3], addr);
#pragma unroll
            for (int ni = 0; ni < 8; ni++) {
                uint32_t bV[2];
                int n = ni * 8 + g;
                bV[0] = __float_as_uint(Vs[(kc + tg) * VLD + n]);
                bV[1] = __float_as_uint(Vs[(kc + tg + 4) * VLD + n]);
                mma_tf32(O[ni], aP, bV);
            }
        }
        __syncthreads();   // K/V[cur] + Ps reads done before overwrite
    }

    // ---- Epilogue: write tf32-rounded ctx ----
    float inv0 = 1.0f / l0;
    float inv1 = 1.0f / l1;
    int row0 = qBase + wrow + g;
#pragma unroll
    for (int ni = 0; ni < 8; ni++) {
        int col = h * DHH + ni * 8 + tg * 2;
        float2 o0 = make_float2(to_tf32(O[ni][0] * inv0), to_tf32(O[ni][1] * inv0));
        float2 o1 = make_float2(to_tf32(O[ni][2] * inv1), to_tf32(O[ni][3] * inv1));
        *reinterpret_cast<float2*>(ctx + ((size_t)(b * NN + row0)) * DD + col) = o0;
        *reinterpret_cast<float2*>(ctx + ((size_t)(b * NN + row0 + 8)) * DD + col) = o1;
    }
}

// ---------------------------------------------------------------------------
// Launch
// ---------------------------------------------------------------------------
extern "C" void kernel_launch(void* const* d_in, const int* in_sizes, int n_in,
                              void* d_out, int out_size) {
    const float* x  = (const float*)d_in[0];
    const float* Wq = (const float*)d_in[1];
    const float* bq = (const float*)d_in[2];
    const float* Wk = (const float*)d_in[3];
    const float* bk = (const float*)d_in[4];
    const float* Wv = (const float*)d_in[5];
    const float* bv = (const float*)d_in[6];
    const float* Wo = (const float*)d_in[7];
    const float* bo = (const float*)d_in[8];
    float* out = (float*)d_out;

    float *qp, *kp, *vp, *cp, *xrp, *wrp;
    cudaGetSymbolAddress((void**)&qp, g_q);
    cudaGetSymbolAddress((void**)&kp, g_k);
    cudaGetSymbolAddress((void**)&vp, g_v);
    cudaGetSymbolAddress((void**)&cp, g_ctx);
    cudaGetSymbolAddress((void**)&xrp, g_xr);
    cudaGetSymbolAddress((void**)&wrp, g_wr);

    cudaFuncSetAttribute(gemm_qkv_kernel,
                         cudaFuncAttributeMaxDynamicSharedMemorySize, GEMM_SMEM);
    cudaFuncSetAttribute(gemm_o_kernel,
                         cudaFuncAttributeMaxDynamicSharedMemorySize, GEMM_SMEM);
    cudaFuncSetAttribute(attn_mma_kernel,
                         cudaFuncAttributeMaxDynamicSharedMemorySize, ATTN_SMEM);

    dim3 roundGrid(M_TOTAL * DD / 4 / 256, 5);   // (4096, 5)
    round_tf32_kernel<<<roundGrid, 256>>>(x, Wq, Wk, Wv, Wo, xrp, wrp);

    dim3 qkvGrid(DD / GBN, M_TOTAL / GBM, 3);    // (8, 32, 3)
    gemm_qkv_kernel<<<qkvGrid, 256, GEMM_SMEM>>>(xrp, wrp, bq, bk, bv, qp, kp, vp);

    dim3 attnGrid(BB * HH, NN / 128);            // (32, 16)
    attn_mma_kernel<<<attnGrid, 256, ATTN_SMEM>>>(qp, kp, vp, cp);

    dim3 gemmGrid(DD / GBN, M_TOTAL / GBM);      // (8, 32)
    gemm_o_kernel<<<gemmGrid, 256, GEMM_SMEM>>>(cp, wrp + (size_t)3 * DD * DD, bo, out);
}

// round 9
// speedup vs baseline: 6.8447x; 1.6678x over previous
#include <cuda_runtime.h>
#include <cuda_fp16.h>
#include <math.h>
#include <stdint.h>

#define BB 2
#define NN 2048
#define DD 1024
#define HH 16
#define DHH 64
#define M_TOTAL (BB * NN)   // 4096

// Scratch (allocation-free rule: __device__ globals)
__device__ __half g_qh[M_TOTAL * DD];
__device__ __half g_kh[M_TOTAL * DD];
__device__ __half g_vh[M_TOTAL * DD];
__device__ __half g_ch[M_TOTAL * DD];
__device__ __half g_xh[M_TOTAL * DD];    // half x
__device__ __half g_wh[4 * DD * DD];     // half Wq,Wk,Wv,Wo

// ---------------------------------------------------------------------------
// Helpers
// ---------------------------------------------------------------------------
__device__ __forceinline__ uint32_t smem_u32(const void* p) {
    uint32_t a;
    asm("{ .reg .u64 t; cvta.to.shared.u64 t, %1; cvt.u32.u64 %0, t; }"
        : "=r"(a) : "l"(p));
    return a;
}

__device__ __forceinline__ void cp16(uint32_t s, const void* g) {
    asm volatile("cp.async.cg.shared.global [%0], [%1], 16;"
                 :: "r"(s), "l"(g));
}
__device__ __forceinline__ void cp_commit() {
    asm volatile("cp.async.commit_group;");
}
template <int N>
__device__ __forceinline__ void cp_wait() {
    asm volatile("cp.async.wait_group %0;" :: "n"(N));
}

// fp16 MMA, fp32 accumulate: D[16x8] += A[16x16] B[16x8]
__device__ __forceinline__ void mma_f16(float* c, const uint32_t* a,
                                        const uint32_t* b) {
    asm volatile(
        "mma.sync.aligned.m16n8k16.row.col.f32.f16.f16.f32 "
        "{%0,%1,%2,%3}, {%4,%5,%6,%7}, {%8,%9}, {%0,%1,%2,%3};"
        : "+f"(c[0]), "+f"(c[1]), "+f"(c[2]), "+f"(c[3])
        : "r"(a[0]), "r"(a[1]), "r"(a[2]), "r"(a[3]), "r"(b[0]), "r"(b[1]));
}

__device__ __forceinline__ void ldsm_x4(uint32_t& r0, uint32_t& r1,
                                        uint32_t& r2, uint32_t& r3,
                                        uint32_t addr) {
    asm volatile("ldmatrix.sync.aligned.m8n8.x4.shared.b16 {%0,%1,%2,%3}, [%4];"
                 : "=r"(r0), "=r"(r1), "=r"(r2), "=r"(r3) : "r"(addr));
}

__device__ __forceinline__ void ldsm_x4_t(uint32_t& r0, uint32_t& r1,
                                          uint32_t& r2, uint32_t& r3,
                                          uint32_t addr) {
    asm volatile("ldmatrix.sync.aligned.m8n8.x4.trans.shared.b16 {%0,%1,%2,%3}, [%4];"
                 : "=r"(r0), "=r"(r1), "=r"(r2), "=r"(r3) : "r"(addr));
}

// exp2 on the FMA/ALU pipes (no MUFU). |rel err| < 6e-5 for f in [-.5,.5].
__device__ __forceinline__ float fexp2(float y) {
    y = fmaxf(y, -120.0f);
    float t = y + 12582912.0f;
    int i = __float_as_int(t) - 0x4B400000;
    float f = y - (t - 12582912.0f);
    float p = 1.0f + f * (0.6931472f + f * (0.24022651f +
              f * (0.05550411f + f * 0.00961813f)));
    return __uint_as_float(__float_as_uint(p) + (i << 23));
}

// ---------------------------------------------------------------------------
// Convert x and the 4 weights to fp16 (once).
// ---------------------------------------------------------------------------
__global__ __launch_bounds__(256)
void to_half_kernel(const float* __restrict__ x,
                    const float* __restrict__ Wq, const float* __restrict__ Wk,
                    const float* __restrict__ Wv, const float* __restrict__ Wo,
                    __half* __restrict__ xh, __half* __restrict__ wh) {
    int z = blockIdx.y;
    int i = blockIdx.x * 256 + threadIdx.x;
    const float* src;
    __half* dst;
    int n4;
    if (z == 0) { src = x; dst = xh; n4 = M_TOTAL * DD / 4; }
    else {
        src = (z == 1) ? Wq : (z == 2) ? Wk : (z == 3) ? Wv : Wo;
        dst = wh + (size_t)(z - 1) * DD * DD;
        n4 = DD * DD / 4;
    }
    if (i < n4) {
        float4 v = reinterpret_cast<const float4*>(src)[i];
        __half2 h01 = __floats2half2_rn(v.x, v.y);
        __half2 h23 = __floats2half2_rn(v.z, v.w);
        uint2 u;
        u.x = *reinterpret_cast<uint32_t*>(&h01);
        u.y = *reinterpret_cast<uint32_t*>(&h23);
        reinterpret_cast<uint2*>(dst)[i] = u;
    }
}

// ---------------------------------------------------------------------------
// 4-stage cp.async fp16 GEMM: Y = X @ W^T + bias.
// CTA tile 128x128, K-chunk 32 halves, 8 warps (2x4), warp 64x32.
// ---------------------------------------------------------------------------
#define GBM 128
#define GBN 128
#define GBK 32                           // halves per K-chunk
#define GLD 40                           // halves row stride
#define GAB (GBM * GLD)                  // halves per tile buffer
#define GSTB (2 * GAB * 2)               // bytes per stage (A+B) = 20480
#define NSTG 4
#define GEMM_SMEM (NSTG * GSTB)          // 81920 B

template <bool OUTH>
__device__ __forceinline__
void gemm_cp_body(const __half* __restrict__ X, const __half* __restrict__ W,
                  const float* __restrict__ bias, void* __restrict__ Yv,
                  int Nd, int K) {
    extern __shared__ char smb[];

    const int tid = threadIdx.x;
    const int wid = tid >> 5;
    const int lane = tid & 31;
    const int g = lane >> 2;
    const int tg = lane & 3;
    const int wm = wid & 1;
    const int wn = wid >> 1;

    const int rowBase = blockIdx.y * GBM;
    const int colBase = blockIdx.x * GBN;

    const uint32_t base = smem_u32(smb);

    // cp.async mapping: 512 16B-chunks per tile, 2 per thread
    const int lrow = tid >> 2;           // 0..63 (+64 for p=1)
    const int lc8 = tid & 3;             // 8-half chunk in row
    const uint32_t loff = (uint32_t)(lrow * GLD + lc8 * 8) * 2u;

    // ldmatrix lane selectors (units: halves)
    const int a_rs = (lane & 7) + ((lane >> 3) & 1) * 8;
    const int a_cs = (lane >> 4) * 8;
    const int b_rs = (lane & 7) + ((lane >> 4) << 3);
    const int b_cs = ((lane >> 3) & 1) * 8;

    float c[4][4][4];
#pragma unroll
    for (int mi = 0; mi < 4; mi++)
#pragma unroll
        for (int ni = 0; ni < 4; ni++)
#pragma unroll
            for (int r = 0; r < 4; r++) c[mi][ni][r] = 0.f;

    const int nstages = K / GBK;         // 32

    auto issue = [&](int s) {
        const uint32_t buf = base + (uint32_t)(s & (NSTG - 1)) * GSTB;
        const int k0 = s * GBK;
        const __half* xa = X + (size_t)(rowBase + lrow) * K + k0 + lc8 * 8;
        const __half* wb = W + (size_t)(colBase + lrow) * K + k0 + lc8 * 8;
#pragma unroll
        for (int p = 0; p < 2; p++) {
            cp16(buf + loff + p * 64 * GLD * 2, xa + (size_t)p * 64 * K);
            cp16(buf + GAB * 2 + loff + p * 64 * GLD * 2, wb + (size_t)p * 64 * K);
        }
        cp_commit();
    };

    issue(0); issue(1); issue(2);

    for (int i = 0; i < nstages; i++) {
        if (i + 2 < nstages) cp_wait<2>();
        else if (i + 1 < nstages) cp_wait<1>();
        else cp_wait<0>();
        __syncthreads();
        if (i + 3 < nstages) issue(i + 3);

        const uint32_t aS = base + (uint32_t)(i & (NSTG - 1)) * GSTB;
        const uint32_t bS = aS + GAB * 2;
#pragma unroll
        for (int kk = 0; kk < GBK / 16; kk++) {
            const int kc = kk * 16;
            uint32_t afrag[4][4];
            uint32_t bfrag[4][2];
#pragma unroll
            for (int mi = 0; mi < 4; mi++) {
                uint32_t addr = aS + (uint32_t)((wm * 64 + mi * 16 + a_rs) * GLD
                                                + kc + a_cs) * 2u;
                ldsm_x4(afrag[mi][0], afrag[mi][1], afrag[mi][2], afrag[mi][3], addr);
            }
#pragma unroll
            for (int p = 0; p < 2; p++) {
                uint32_t addr = bS + (uint32_t)((wn * 32 + p * 16 + b_rs) * GLD
                                                + kc + b_cs) * 2u;
                ldsm_x4(bfrag[2 * p][0], bfrag[2 * p][1],
                        bfrag[2 * p + 1][0], bfrag[2 * p + 1][1], addr);
            }
#pragma unroll
            for (int mi = 0; mi < 4; mi++)
#pragma unroll
                for (int ni = 0; ni < 4; ni++)
                    mma_f16(c[mi][ni], afrag[mi], bfrag[ni]);
        }
    }

#pragma unroll
    for (int mi = 0; mi < 4; mi++) {
        int row0 = rowBase + wm * 64 + mi * 16 + g;
#pragma unroll
        for (int ni = 0; ni < 4; ni++) {
            int col = colBase + wn * 32 + ni * 8 + tg * 2;
            float2 bv = *reinterpret_cast<const float2*>(bias + col);
            if (OUTH) {
                __half* Y = (__half*)Yv;
                __half2 h0 = __floats2half2_rn(c[mi][ni][0] + bv.x, c[mi][ni][1] + bv.y);
                __half2 h1 = __floats2half2_rn(c[mi][ni][2] + bv.x, c[mi][ni][3] + bv.y);
                *reinterpret_cast<__half2*>(Y + (size_t)row0 * Nd + col) = h0;
                *reinterpret_cast<__half2*>(Y + (size_t)(row0 + 8) * Nd + col) = h1;
            } else {
                float* Y = (float*)Yv;
                float2 o0 = make_float2(c[mi][ni][0] + bv.x, c[mi][ni][1] + bv.y);
                float2 o1 = make_float2(c[mi][ni][2] + bv.x, c[mi][ni][3] + bv.y);
                *reinterpret_cast<float2*>(Y + (size_t)row0 * Nd + col) = o0;
                *reinterpret_cast<float2*>(Y + (size_t)(row0 + 8) * Nd + col) = o1;
            }
        }
    }
}

__global__ __launch_bounds__(256, 2)
void gemm_qkv_kernel(const __half* __restrict__ Xh, const __half* __restrict__ Wh,
                     const float* __restrict__ bq, const float* __restrict__ bk,
                     const float* __restrict__ bv,
                     __half* __restrict__ q, __half* __restrict__ kk,
                     __half* __restrict__ vv) {
    const int z = blockIdx.z;
    const __half* W = Wh + (size_t)z * DD * DD;
    const float* bias = (z == 0) ? bq : (z == 1) ? bk : bv;
    __half* Y = (z == 0) ? q : (z == 1) ? kk : vv;
    gemm_cp_body<true>(Xh, W, bias, Y, DD, DD);
}

__global__ __launch_bounds__(256, 2)
void gemm_o_kernel(const __half* __restrict__ ctx, const __half* __restrict__ Woh,
                   const float* __restrict__ bo, float* __restrict__ out) {
    gemm_cp_body<false>(ctx, Woh, bo, out, DD, DD);
}

// ---------------------------------------------------------------------------
// fp16 tensor-core flash attention: cp.async K/V double buffer + ldmatrix.
// Block: 256 threads = 8 warps; qtile 128; ktile 64.
// smem (halves): Ps[128][72] | K0[64][72] | V0[64][72] | K1 | V1 = 54 KB.
// ---------------------------------------------------------------------------
#define PLD 72
#define KLD 72
#define VLD 72
#define PS_H (128 * PLD)
#define KS_H (64 * KLD)
#define VS_H (64 * VLD)
#define ATTN_SMEM ((PS_H + 2 * (KS_H + VS_H)) * 2)

__global__ __launch_bounds__(256, 2)
void attn_mma_kernel(const __half* __restrict__ q, const __half* __restrict__ k,
                     const __half* __restrict__ v, __half* __restrict__ ctx) {
    extern __shared__ char smb[];
    __half* Ps = (__half*)smb;

    const int tid = threadIdx.x;
    const int wid = tid >> 5;
    const int lane = tid & 31;
    const int g = lane >> 2;
    const int tg = lane & 3;
    const int wrow = wid * 16;

    const int bh = blockIdx.x;
    const int b = bh / HH;
    const int h = bh % HH;
    const int qBase = blockIdx.y * 128;

    const float cscale = 0.18033688f;   // (1/8) * log2(e)

    const __half* kbase = k + ((size_t)(b * NN)) * DD + h * DHH;
    const __half* vbase = v + ((size_t)(b * NN)) * DD + h * DHH;

    const uint32_t base = smem_u32(smb);
    const uint32_t kvbase[2] = { base + PS_H * 2,
                                 base + (PS_H + KS_H + VS_H) * 2 };

    // K/V cp mapping: 64 rows x 8 chunks (8 halves) = 512; 2 per thread
    const int lrow = tid >> 3;           // 0..31 (+32 for p=1)
    const int lc8 = tid & 7;

    // ldmatrix lane selectors (halves)
    const int a_rs = (lane & 7) + ((lane >> 3) & 1) * 8;
    const int a_cs = (lane >> 4) * 8;
    const int b_rs = (lane & 7) + ((lane >> 4) << 3);
    const int b_cs = ((lane >> 3) & 1) * 8;
    const int v_rs = (lane & 7) + ((lane >> 3) & 1) * 8;   // k-dim rows
    const int v_cs = (lane >> 4) * 8;                      // n offset

    // ---- Issue K/V tile 0 ----
    {
        const __half* kp = kbase + (size_t)lrow * DD + lc8 * 8;
        const __half* vp = vbase + (size_t)lrow * DD + lc8 * 8;
#pragma unroll
        for (int p = 0; p < 2; p++) {
            uint32_t ro = (uint32_t)((lrow + p * 32) * KLD + lc8 * 8) * 2u;
            cp16(kvbase[0] + ro, kp + (size_t)p * 32 * DD);
            cp16(kvbase[0] + KS_H * 2 + ro, vp + (size_t)p * 32 * DD);
        }
        cp_commit();
    }

    // ---- Load Q tile (128 x 64 halves) into Ps ----
    {
        const __half* qsrc = q + ((size_t)(b * NN + qBase)) * DD + h * DHH;
#pragma unroll
        for (int p = 0; p < 4; p++) {
            int idx = p * 256 + tid;     // 1024 chunks of 8 halves
            int row = idx >> 3;
            int c8 = idx & 7;
            uint4 a = *reinterpret_cast<const uint4*>(qsrc + (size_t)row * DD + c8 * 8);
            *reinterpret_cast<uint4*>(&Ps[row * PLD + c8 * 8]) = a;
        }
    }
    __syncthreads();

    // ---- Q fragments -> registers (4 k16-steps over 64) ----
    uint32_t aQ[4][4];
#pragma unroll
    for (int kk = 0; kk < 4; kk++) {
        uint32_t addr = base + (uint32_t)((wrow + a_rs) * PLD + kk * 16 + a_cs) * 2u;
        ldsm_x4(aQ[kk][0], aQ[kk][1], aQ[kk][2], aQ[kk][3], addr);
    }

    float m0 = -1e30f, m1 = -1e30f, l0 = 0.f, l1 = 0.f;
    float O[8][4];
#pragma unroll
    for (int ni = 0; ni < 8; ni++)
#pragma unroll
        for (int r = 0; r < 4; r++) O[ni][r] = 0.f;

    const int ntiles = NN / 64;
    for (int i = 0; i < ntiles; i++) {
        const int cur = i & 1;

        if (i + 1 < ntiles) {
            const __half* kp = kbase + (size_t)((i + 1) * 64 + lrow) * DD + lc8 * 8;
            const __half* vp = vbase + (size_t)((i + 1) * 64 + lrow) * DD + lc8 * 8;
            const uint32_t dst = kvbase[cur ^ 1];
#pragma unroll
            for (int p = 0; p < 2; p++) {
                uint32_t ro = (uint32_t)((lrow + p * 32) * KLD + lc8 * 8) * 2u;
                cp16(dst + ro, kp + (size_t)p * 32 * DD);
                cp16(dst + KS_H * 2 + ro, vp + (size_t)p * 32 * DD);
            }
            cp_commit();
            cp_wait<1>();
        } else {
            cp_wait<0>();
        }
        __syncthreads();

        const uint32_t ksU = kvbase[cur];
        const uint32_t vsU = ksU + KS_H * 2;

        // ---- S = Q K^T ----
        float S[8][4];
#pragma unroll
        for (int ni = 0; ni < 8; ni++)
#pragma unroll
            for (int r = 0; r < 4; r++) S[ni][r] = 0.f;
#pragma unroll
        for (int kk = 0; kk < 4; kk++) {
            const int kc = kk * 16;
#pragma unroll
            for (int p = 0; p < 4; p++) {
                uint32_t bK[4];
                uint32_t addr = ksU + (uint32_t)((p * 16 + b_rs) * KLD + kc + b_cs) * 2u;
                ldsm_x4(bK[0], bK[1], bK[2], bK[3], addr);
                mma_f16(S[2 * p], aQ[kk], bK);
                mma_f16(S[2 * p + 1], aQ[kk], bK + 2);
            }
        }

        // ---- Online softmax (log2 domain) ----
        float ym0 = -1e30f, ym1 = -1e30f;
#pragma unroll
        for (int ni = 0; ni < 8; ni++) {
            ym0 = fmaxf(ym0, fmaxf(S[ni][0], S[ni][1]));
            ym1 = fmaxf(ym1, fmaxf(S[ni][2], S[ni][3]));
        }
        ym0 = fmaxf(ym0, __shfl_xor_sync(0xffffffffu, ym0, 1));
        ym0 = fmaxf(ym0, __shfl_xor_sync(0xffffffffu, ym0, 2));
        ym1 = fmaxf(ym1, __shfl_xor_sync(0xffffffffu, ym1, 1));
        ym1 = fmaxf(ym1, __shfl_xor_sync(0xffffffffu, ym1, 2));
        float mn0 = fmaxf(m0, ym0 * cscale);
        float mn1 = fmaxf(m1, ym1 * cscale);
        float al0 = fexp2(m0 - mn0);
        float al1 = fexp2(m1 - mn1);

        float ls0 = 0.f, ls1 = 0.f;
        int r0 = wrow + g;
#pragma unroll
        for (int ni = 0; ni < 8; ni++) {
            float p0 = fexp2(fmaf(S[ni][0], cscale, -mn0));
            float p1 = fexp2(fmaf(S[ni][1], cscale, -mn0));
            float p2 = fexp2(fmaf(S[ni][2], cscale, -mn1));
            float p3 = fexp2(fmaf(S[ni][3], cscale, -mn1));
            ls0 += p0 + p1;
            ls1 += p2 + p3;
            int col = ni * 8 + tg * 2;
            *reinterpret_cast<__half2*>(&Ps[r0 * PLD + col]) = __floats2half2_rn(p0, p1);
            *reinterpret_cast<__half2*>(&Ps[(r0 + 8) * PLD + col]) = __floats2half2_rn(p2, p3);
        }
        ls0 += __shfl_xor_sync(0xffffffffu, ls0, 1);
        ls0 += __shfl_xor_sync(0xffffffffu, ls0, 2);
        ls1 += __shfl_xor_sync(0xffffffffu, ls1, 1);
        ls1 += __shfl_xor_sync(0xffffffffu, ls1, 2);

        l0 = l0 * al0 + ls0;
        l1 = l1 * al1 + ls1;
        m0 = mn0;
        m1 = mn1;
#pragma unroll
        for (int ni = 0; ni < 8; ni++) {
            O[ni][0] *= al0; O[ni][1] *= al0;
            O[ni][2] *= al1; O[ni][3] *= al1;
        }
        __syncwarp();

        // ---- O += P V (V via ldmatrix.trans) ----
#pragma unroll
        for (int kk = 0; kk < 4; kk++) {
            const int kc = kk * 16;
            uint32_t aP[4];
            uint32_t addr = base + (uint32_t)((wrow + a_rs) * PLD + kc + a_cs) * 2u;
            ldsm_x4(aP[0], aP[1], aP[2], aP[3], addr);
#pragma unroll
            for (int p = 0; p < 4; p++) {
                uint32_t bV[4];
                uint32_t va = vsU + (uint32_t)((kc + v_rs) * VLD + p * 16 + v_cs) * 2u;
                ldsm_x4_t(bV[0], bV[1], bV[2], bV[3], va);
                mma_f16(O[2 * p], aP, bV);
                mma_f16(O[2 * p + 1], aP, bV + 2);
            }
        }
        __syncthreads();   // K/V[cur] + Ps reads done before overwrite
    }

    // ---- Epilogue: write half ctx ----
    float inv0 = 1.0f / l0;
    float inv1 = 1.0f / l1;
    int row0 = qBase + wrow + g;
#pragma unroll
    for (int ni = 0; ni < 8; ni++) {
        int col = h * DHH + ni * 8 + tg * 2;
        __half2 h0 = __floats2half2_rn(O[ni][0] * inv0, O[ni][1] * inv0);
        __half2 h1 = __floats2half2_rn(O[ni][2] * inv1, O[ni][3] * inv1);
        *reinterpret_cast<__half2*>(ctx + ((size_t)(b * NN + row0)) * DD + col) = h0;
        *reinterpret_cast<__half2*>(ctx + ((size_t)(b * NN + row0 + 8)) * DD + col) = h1;
    }
}

// ---------------------------------------------------------------------------
// Launch
// ---------------------------------------------------------------------------
extern "C" void kernel_launch(void* const* d_in, const int* in_sizes, int n_in,
                              void* d_out, int out_size) {
    const float* x  = (const float*)d_in[0];
    const float* Wq = (const float*)d_in[1];
    const float* bq = (const float*)d_in[2];
    const float* Wk = (const float*)d_in[3];
    const float* bk = (const float*)d_in[4];
    const float* Wv = (const float*)d_in[5];
    const float* bv = (const float*)d_in[6];
    const float* Wo = (const float*)d_in[7];
    const float* bo = (const float*)d_in[8];
    float* out = (float*)d_out;

    __half *qp, *kp, *vp, *cp, *xhp, *whp;
    cudaGetSymbolAddress((void**)&qp, g_qh);
    cudaGetSymbolAddress((void**)&kp, g_kh);
    cudaGetSymbolAddress((void**)&vp, g_vh);
    cudaGetSymbolAddress((void**)&cp, g_ch);
    cudaGetSymbolAddress((void**)&xhp, g_xh);
    cudaGetSymbolAddress((void**)&whp, g_wh);

    cudaFuncSetAttribute(gemm_qkv_kernel,
                         cudaFuncAttributeMaxDynamicSharedMemorySize, GEMM_SMEM);
    cudaFuncSetAttribute(gemm_o_kernel,
                         cudaFuncAttributeMaxDynamicSharedMemorySize, GEMM_SMEM);
    cudaFuncSetAttribute(attn_mma_kernel,
                         cudaFuncAttributeMaxDynamicSharedMemorySize, ATTN_SMEM);

    dim3 cvtGrid(M_TOTAL * DD / 4 / 256, 5);     // (4096, 5)
    to_half_kernel<<<cvtGrid, 256>>>(x, Wq, Wk, Wv, Wo, xhp, whp);

    dim3 qkvGrid(DD / GBN, M_TOTAL / GBM, 3);    // (8, 32, 3)
    gemm_qkv_kernel<<<qkvGrid, 256, GEMM_SMEM>>>(xhp, whp, bq, bk, bv, qp, kp, vp);

    dim3 attnGrid(BB * HH, NN / 128);            // (32, 16)
    attn_mma_kernel<<<attnGrid, 256, ATTN_SMEM>>>(qp, kp, vp, cp);

    dim3 gemmGrid(DD / GBN, M_TOTAL / GBM);      // (8, 32)
    gemm_o_kernel<<<gemmGrid, 256, GEMM_SMEM>>>(cp, whp + (size_t)3 * DD * DD, bo, out);
}